// round 11
// baseline (speedup 1.0000x reference)
#include <cuda_runtime.h>

#define FULLMASK 0xffffffffu

// Problem dims (fixed by the dataset)
#define Bb 16
#define Ss 256
#define Nn 16
#define Dd 6
#define Hh 16
#define CHAINS 256
#define NSEG 16
#define SEGL 16

// Per-row projection partials: [row][hq][d] = 65536 x 24 floats = 6.3 MB
__device__ float g_part[(size_t)CHAINS * Ss * 24];

// ---- Clifford sign machinery (5-bit blade masks, matches reference) ----
__host__ __device__ constexpr unsigned popc5(unsigned v) {
    v &= 31u;
    return (v & 1u) + ((v >> 1) & 1u) + ((v >> 2) & 1u) + ((v >> 3) & 1u) + ((v >> 4) & 1u);
}
__host__ __device__ constexpr int csn(unsigned a, unsigned b) {
    a >>= 1; int s = 0;
    while (a) { s += (int)popc5(a & b); a >>= 1; }
    return s & 1;
}
__host__ __device__ constexpr unsigned lift4(unsigned L) {
    L &= 15u;
    unsigned p = (L ^ (L >> 1) ^ (L >> 2) ^ (L >> 3)) & 1u;
    return L | (p << 4);
}
__host__ __device__ constexpr unsigned long long buildCT() {
    unsigned long long t = 0;
    for (unsigned m = 0; m < 4; ++m)
        for (unsigned s = 0; s < 4; ++s)
            for (unsigned jr = 0; jr < 4; ++jr)
                if (csn(lift4((m << 2) | s), lift4(jr)))
                    t |= 1ull << (m * 16 + s * 4 + jr);
    return t;
}
static constexpr unsigned long long CT_TABLE = buildCT();
#define CT(m, s, jr) (int)((CT_TABLE >> ((m) * 16 + (s) * 4 + (jr))) & 1ull)

// One mask-m term of out = A*B (16-dim split-ideal XOR-conv).
#define GP_MASK(M, dv, SMC, pm0, pm1, pm2, pm3, q0, q1, q2, q3) do {            \
    const float as0 = __uint_as_float(__float_as_uint((dv).x) ^ (SMC)[0]);      \
    const float as1 = __uint_as_float(__float_as_uint((dv).y) ^ (SMC)[1]);      \
    const float as2 = __uint_as_float(__float_as_uint((dv).z) ^ (SMC)[2]);      \
    const float as3 = __uint_as_float(__float_as_uint((dv).w) ^ (SMC)[3]);      \
    q0 = fmaf(CT(M,0,0) ? -as0 : as0, pm0, q0);                                 \
    q1 = fmaf(CT(M,0,1) ? -as0 : as0, pm1, q1);                                 \
    q2 = fmaf(CT(M,0,2) ? -as0 : as0, pm2, q2);                                 \
    q3 = fmaf(CT(M,0,3) ? -as0 : as0, pm3, q3);                                 \
    q0 = fmaf(CT(M,1,1) ? -as1 : as1, pm1, q0);                                 \
    q1 = fmaf(CT(M,1,0) ? -as1 : as1, pm0, q1);                                 \
    q2 = fmaf(CT(M,1,3) ? -as1 : as1, pm3, q2);                                 \
    q3 = fmaf(CT(M,1,2) ? -as1 : as1, pm2, q3);                                 \
    q0 = fmaf(CT(M,2,2) ? -as2 : as2, pm2, q0);                                 \
    q1 = fmaf(CT(M,2,3) ? -as2 : as2, pm3, q1);                                 \
    q2 = fmaf(CT(M,2,0) ? -as2 : as2, pm0, q2);                                 \
    q3 = fmaf(CT(M,2,1) ? -as2 : as2, pm1, q3);                                 \
    q0 = fmaf(CT(M,3,3) ? -as3 : as3, pm3, q0);                                 \
    q1 = fmaf(CT(M,3,2) ? -as3 : as3, pm2, q1);                                 \
    q2 = fmaf(CT(M,3,1) ? -as3 : as3, pm1, q2);                                 \
    q3 = fmaf(CT(M,3,0) ? -as3 : as3, pm0, q3);                                 \
} while (0)

__device__ __forceinline__ void build_smC(int g2, unsigned smC[4][4]) {
#pragma unroll
    for (int m = 0; m < 4; ++m) {
        const unsigned jhi = lift4((unsigned)(((g2 ^ m) & 3) << 2));
#pragma unroll
        for (int s = 0; s < 4; ++s)
            smC[m][s] = (unsigned)csn(lift4((unsigned)((m << 2) | s)), jhi) << 31;
    }
}

// SMEM layout (float4 units): sP[256][32] | sD[16][2][32] | sC[16][32]
#define SP_ENT (256 * 32)
#define SD_ENT (16 * 2 * 32)
#define SC_ENT (16 * 32)
#define SMEM_BYTES ((SP_ENT + SD_ENT + SC_ENT) * 16)

// ---------------------------------------------------------------------------
// Fused scan kernel. Block = (chain, headquad): 512 threads (16 warps), one
// warp per segment. P never leaves SMEM.
// ---------------------------------------------------------------------------
__global__ void __launch_bounds__(512) fused_kernel(
    const float* __restrict__ x,      // [B,S,N,D]
    const float* __restrict__ W_in,   // [D, H*32]
    const float* __restrict__ b_in,   // [H*32]
    const float* __restrict__ W_out)  // [H*32, D]
{
    extern __shared__ float4 smem[];
    float4* sP = smem;                 // [step][lane], step = seg*16+i
    float4* sD = smem + SP_ENT;        // [warp][buf][lane]
    float4* sC = smem + SP_ENT + SD_ENT; // [seg][lane]

    const int wid  = threadIdx.x >> 5;     // segment 0..15
    const int lane = threadIdx.x & 31;
    const int c  = blockIdx.x >> 2;
    const int hq = blockIdx.x & 3;
    const int hw   = lane >> 3;
    const int half = (lane >> 2) & 1;
    const int g2   = lane & 3;
    const int h  = hq * 4 + hw;
    const int b  = c >> 4;
    const int n  = c & (Nn - 1);
    const int dlbase = lane & 28;
    const int seg = wid;

    unsigned smC[4][4];
    build_smC(g2, smC);

    // ---- transformed input weights (per lane) ----
    float wi[4][Dd], bi[4];
#pragma unroll
    for (int r = 0; r < 4; ++r) {
        const unsigned E  = lift4((unsigned)(g2 * 4 + r));
        const unsigned Ed = E ^ 31u;
        const float sIn  = csn(31u, Ed) ? -1.0f : 1.0f;
        const float coef = half ? -sIn : sIn;
        const int colE = h * 32 + (int)E, colD = h * 32 + (int)Ed;
#pragma unroll
        for (int d = 0; d < Dd; ++d)
            wi[r][d] = __ldg(W_in + d * 512 + colE) + coef * __ldg(W_in + d * 512 + colD);
        bi[r] = __ldg(b_in + colE) + coef * __ldg(b_in + colD);
    }

    // =========================== Phase A ===================================
    // local prefixes P_{seg,i} = dl_i * ... * dl_0, stored to sP rows
    {
        float w0 = 0.f, w1 = 0.f, w2 = 0.f, w3 = 0.f;
        const float* xp = x + (((size_t)b * Ss + seg * SEGL) * Nn + n) * Dd;

#pragma unroll 1
        for (int i = 0; i < SEGL; ++i) {
            float cx[Dd];
#pragma unroll
            for (int d = 0; d < Dd; ++d) cx[d] = __ldg(xp + d);
            xp += Nn * Dd;

            // dl = transformed (x@W_in + b_in ; +1 at label 0)
            float dl0 = bi[0], dl1 = bi[1], dl2 = bi[2], dl3 = bi[3];
#pragma unroll
            for (int d = 0; d < Dd; ++d) {
                dl0 = fmaf(wi[0][d], cx[d], dl0);
                dl1 = fmaf(wi[1][d], cx[d], dl1);
                dl2 = fmaf(wi[2][d], cx[d], dl2);
                dl3 = fmaf(wi[3][d], cx[d], dl3);
            }
            if (g2 == 0) dl0 += 1.0f;

            if (i == 0) {
                // GP(dl, identity) = dl
                w0 = dl0; w1 = dl1; w2 = dl2; w3 = dl3;
            } else {
                const int buf = i & 1;
                sD[(wid * 2 + buf) * 32 + lane] = make_float4(dl0, dl1, dl2, dl3);
                __syncwarp();

                const int prow = seg * SEGL + i - 1;
                float pA0 = 0.f, pA1 = 0.f, pA2 = 0.f, pA3 = 0.f;
                float pB0 = 0.f, pB1 = 0.f, pB2 = 0.f, pB3 = 0.f;
                {   const float4 dv = sD[(wid * 2 + buf) * 32 + dlbase];
                    GP_MASK(0, dv, smC[0], w0, w1, w2, w3, pA0, pA1, pA2, pA3);
                }
                {   const float4 wv = sP[prow * 32 + (lane ^ 1)];
                    const float4 dv = sD[(wid * 2 + buf) * 32 + (dlbase | 1)];
                    GP_MASK(1, dv, smC[1], wv.x, wv.y, wv.z, wv.w, pB0, pB1, pB2, pB3);
                }
                {   const float4 wv = sP[prow * 32 + (lane ^ 2)];
                    const float4 dv = sD[(wid * 2 + buf) * 32 + (dlbase | 2)];
                    GP_MASK(2, dv, smC[2], wv.x, wv.y, wv.z, wv.w, pA0, pA1, pA2, pA3);
                }
                {   const float4 wv = sP[prow * 32 + (lane ^ 3)];
                    const float4 dv = sD[(wid * 2 + buf) * 32 + (dlbase | 3)];
                    GP_MASK(3, dv, smC[3], wv.x, wv.y, wv.z, wv.w, pB0, pB1, pB2, pB3);
                }
                w0 = pA0 + pB0; w1 = pA1 + pB1; w2 = pA2 + pB2; w3 = pA3 + pB3;
            }
            sP[(seg * SEGL + i) * 32 + lane] = make_float4(w0, w1, w2, w3);
        }
    }
    __syncthreads();

    // =========================== Phase B ===================================
    // warp 0: C_{s+1} = normalize(T_s * C_s), T_s = sP[s*16+15]
    if (wid == 0) {
        float c0 = (g2 == 0) ? 1.0f : 0.0f, c1 = 0.f, c2 = 0.f, c3 = 0.f;
#pragma unroll 1
        for (int s = 0; s < NSEG; ++s) {
            const int buf = s & 1;
            sC[s * 32 + lane] = make_float4(c0, c1, c2, c3);

            const float4 T = sP[(s * SEGL + SEGL - 1) * 32 + lane];
            sD[(0 * 2 + buf) * 32 + lane] = T;                       // dv side
            sD[(1 * 2 + buf) * 32 + lane] = make_float4(c0, c1, c2, c3); // wv side
            __syncwarp();

            float pA0 = 0.f, pA1 = 0.f, pA2 = 0.f, pA3 = 0.f;
            float pB0 = 0.f, pB1 = 0.f, pB2 = 0.f, pB3 = 0.f;
            {   const float4 dv = sD[(0 * 2 + buf) * 32 + dlbase];
                GP_MASK(0, dv, smC[0], c0, c1, c2, c3, pA0, pA1, pA2, pA3);
            }
            {   const float4 wv = sD[(1 * 2 + buf) * 32 + (lane ^ 1)];
                const float4 dv = sD[(0 * 2 + buf) * 32 + (dlbase | 1)];
                GP_MASK(1, dv, smC[1], wv.x, wv.y, wv.z, wv.w, pB0, pB1, pB2, pB3);
            }
            {   const float4 wv = sD[(1 * 2 + buf) * 32 + (lane ^ 2)];
                const float4 dv = sD[(0 * 2 + buf) * 32 + (dlbase | 2)];
                GP_MASK(2, dv, smC[2], wv.x, wv.y, wv.z, wv.w, pA0, pA1, pA2, pA3);
            }
            {   const float4 wv = sD[(1 * 2 + buf) * 32 + (lane ^ 3)];
                const float4 dv = sD[(0 * 2 + buf) * 32 + (dlbase | 3)];
                GP_MASK(3, dv, smC[3], wv.x, wv.y, wv.z, wv.w, pB0, pB1, pB2, pB3);
            }
            float n0 = pA0 + pB0, n1 = pA1 + pB1, n2 = pA2 + pB2, n3 = pA3 + pB3;

            // scale-only normalize
            float ss = n0 * n0 + n1 * n1;
            ss = fmaf(n2, n2, ss);
            ss = fmaf(n3, n3, ss);
            ss += __shfl_xor_sync(FULLMASK, ss, 1);
            ss += __shfl_xor_sync(FULLMASK, ss, 2);
            ss += __shfl_xor_sync(FULLMASK, ss, 4);
            const float r = rsqrtf(ss + 1e-30f);
            c0 = n0 * r; c1 = n1 * r; c2 = n2 * r; c3 = n3 * r;
        }
    }
    __syncthreads();

    // =========================== Phase C ===================================
    // psi_t = P_{seg,i} * C_seg ; exact normalize ; fused projection.
    {
        // transformed output weights
        float wo[4][Dd];
#pragma unroll
        for (int r = 0; r < 4; ++r) {
            const unsigned E  = lift4((unsigned)(g2 * 4 + r));
            const unsigned Ed = E ^ 31u;
            const float sOut = csn(31u, E) ? -1.0f : 1.0f;
            const float coef = half ? -sOut : sOut;
            const int colE = h * 32 + (int)E, colD = h * 32 + (int)Ed;
#pragma unroll
            for (int d = 0; d < Dd; ++d)
                wo[r][d] = __ldg(W_out + colE * Dd + d) + coef * __ldg(W_out + colD * Dd + d);
        }

        float4 Creg[4];
#pragma unroll
        for (int m = 0; m < 4; ++m) Creg[m] = sC[seg * 32 + (lane ^ m)];

        float* pw = g_part + ((size_t)(c * Ss + seg * SEGL)) * 24 + hq * 6 + lane;

#pragma unroll 1
        for (int i = 0; i < SEGL; ++i) {
            const int row = seg * SEGL + i;
            float pA0 = 0.f, pA1 = 0.f, pA2 = 0.f, pA3 = 0.f;
            float pB0 = 0.f, pB1 = 0.f, pB2 = 0.f, pB3 = 0.f;
            {   const float4 dv = sP[row * 32 + dlbase];
                GP_MASK(0, dv, smC[0], Creg[0].x, Creg[0].y, Creg[0].z, Creg[0].w,
                        pA0, pA1, pA2, pA3);
            }
            {   const float4 dv = sP[row * 32 + (dlbase | 1)];
                GP_MASK(1, dv, smC[1], Creg[1].x, Creg[1].y, Creg[1].z, Creg[1].w,
                        pB0, pB1, pB2, pB3);
            }
            {   const float4 dv = sP[row * 32 + (dlbase | 2)];
                GP_MASK(2, dv, smC[2], Creg[2].x, Creg[2].y, Creg[2].z, Creg[2].w,
                        pA0, pA1, pA2, pA3);
            }
            {   const float4 dv = sP[row * 32 + (dlbase | 3)];
                GP_MASK(3, dv, smC[3], Creg[3].x, Creg[3].y, Creg[3].z, Creg[3].w,
                        pB0, pB1, pB2, pB3);
            }
            const float nw0 = pA0 + pB0, nw1 = pA1 + pB1;
            const float nw2 = pA2 + pB2, nw3 = pA3 + pB3;

            // exact normalize: |psi|^2 = 2*(per-head 8-lane sum), + NR step
            float s = nw0 * nw0 + nw1 * nw1;
            s = fmaf(nw2, nw2, s);
            s = fmaf(nw3, nw3, s);
            s += __shfl_xor_sync(FULLMASK, s, 1);
            s += __shfl_xor_sync(FULLMASK, s, 2);
            s += __shfl_xor_sync(FULLMASK, s, 4);
            s = s + s + 1e-30f;
            float rn = rsqrtf(s);
            rn = rn * (1.5f - 0.5f * s * rn * rn);
            const float st0 = nw0 * rn, st1 = nw1 * rn;
            const float st2 = nw2 * rn, st3 = nw3 * rn;

            // projection partials
            float p0, p1, p2, p3, p4, p5;
            p0 = st0 * wo[0][0]; p1 = st0 * wo[0][1]; p2 = st0 * wo[0][2];
            p3 = st0 * wo[0][3]; p4 = st0 * wo[0][4]; p5 = st0 * wo[0][5];
            p0 = fmaf(st1, wo[1][0], p0); p1 = fmaf(st1, wo[1][1], p1);
            p2 = fmaf(st1, wo[1][2], p2); p3 = fmaf(st1, wo[1][3], p3);
            p4 = fmaf(st1, wo[1][4], p4); p5 = fmaf(st1, wo[1][5], p5);
            p0 = fmaf(st2, wo[2][0], p0); p1 = fmaf(st2, wo[2][1], p1);
            p2 = fmaf(st2, wo[2][2], p2); p3 = fmaf(st2, wo[2][3], p3);
            p4 = fmaf(st2, wo[2][4], p4); p5 = fmaf(st2, wo[2][5], p5);
            p0 = fmaf(st3, wo[3][0], p0); p1 = fmaf(st3, wo[3][1], p1);
            p2 = fmaf(st3, wo[3][2], p2); p3 = fmaf(st3, wo[3][3], p3);
            p4 = fmaf(st3, wo[3][4], p4); p5 = fmaf(st3, wo[3][5], p5);
            // full 32-lane reduce: sums both halves AND the quad's 4 heads
#pragma unroll
            for (int o = 1; o < 32; o <<= 1) {
                p0 += __shfl_xor_sync(FULLMASK, p0, o);
                p1 += __shfl_xor_sync(FULLMASK, p1, o);
                p2 += __shfl_xor_sync(FULLMASK, p2, o);
                p3 += __shfl_xor_sync(FULLMASK, p3, o);
                p4 += __shfl_xor_sync(FULLMASK, p4, o);
                p5 += __shfl_xor_sync(FULLMASK, p5, o);
            }
            const float pv = (lane == 0) ? p0 : (lane == 1) ? p1 : (lane == 2) ? p2
                           : (lane == 3) ? p3 : (lane == 4) ? p4 : p5;
            if (lane < 6) *pw = pv;
            pw += 24;
        }
    }
}

// ---------------------------------------------------------------------------
// Combine: y[row,d] = x[row,d] + b_out[d] + sum_{4 hq} g_part[row][hq][d]
// ---------------------------------------------------------------------------
__global__ void __launch_bounds__(256) combine_kernel(
    const float* __restrict__ x,
    const float* __restrict__ b_out,
    float* __restrict__ y)
{
    const int e   = blockIdx.x * blockDim.x + threadIdx.x;  // 0..393215
    const int row = e / 6;              // chain*256 + t
    const int d   = e - row * 6;

    const float* pp = g_part + (size_t)row * 24 + d;
    float acc = __ldg(b_out + d)
              + (__ldg(pp) + __ldg(pp + 6)) + (__ldg(pp + 12) + __ldg(pp + 18));

    const int c = row >> 8;
    const int t = row & (Ss - 1);
    const int b = c >> 4;
    const int n = c & (Nn - 1);
    const size_t off = (((size_t)b * Ss + t) * Nn + n) * Dd + d;
    y[off] = __ldg(x + off) + acc;
}

extern "C" void kernel_launch(void* const* d_in, const int* in_sizes, int n_in,
                              void* d_out, int out_size) {
    const float* x     = (const float*)d_in[0];
    const float* W_in  = (const float*)d_in[1];
    const float* b_in  = (const float*)d_in[2];
    const float* W_out = (const float*)d_in[3];
    const float* b_out = (const float*)d_in[4];
    float* y = (float*)d_out;

    static int attr_set = 0;
    if (!attr_set) {
        cudaFuncSetAttribute(fused_kernel,
                             cudaFuncAttributeMaxDynamicSharedMemorySize, SMEM_BYTES);
        attr_set = 1;
    }

    // Fused scan: 1024 blocks = 256 chains x 4 head-quads, 512 threads each
    fused_kernel<<<1024, 512, SMEM_BYTES>>>(x, W_in, b_in, W_out);
    // Combine
    combine_kernel<<<1536, 256>>>(x, b_out, y);
}

// round 12
// speedup vs baseline: 1.2227x; 1.2227x over previous
#include <cuda_runtime.h>

#define FULLMASK 0xffffffffu

// Problem dims (fixed by the dataset)
#define Bb 16
#define Ss 256
#define Nn 16
#define Dd 6

// Per-row projection partials, layout [row][d*16 + head] = 25 MB
__device__ float g_part[(size_t)256 * 256 * 96];

// ---- Clifford sign machinery (5-bit blade masks, matches reference) ----
__host__ __device__ constexpr unsigned popc5(unsigned v) {
    v &= 31u;
    return (v & 1u) + ((v >> 1) & 1u) + ((v >> 2) & 1u) + ((v >> 3) & 1u) + ((v >> 4) & 1u);
}
__host__ __device__ constexpr int csn(unsigned a, unsigned b) {
    a >>= 1; int s = 0;
    while (a) { s += (int)popc5(a & b); a >>= 1; }
    return s & 1;
}
// lift 4-bit even-subalgebra label -> 5-bit even blade mask
__host__ __device__ constexpr unsigned lift4(unsigned L) {
    L &= 15u;
    unsigned p = (L ^ (L >> 1) ^ (L >> 2) ^ (L >> 3)) & 1u;
    return L | (p << 4);
}
// quaternion unit product sign: dims XOR; neg iff bit(d1*4+d2) of 0xC6A0
#define QNEG(d1, d2) ((0xC6A0u >> ((d1) * 4 + (d2))) & 1u)

// ---------------------------------------------------------------------------
// Rotor recurrence + fused projection, M2(H) representation of each ideal.
// Warp = (chain, head-quad). lane = h*8 + half*4 + q, q = r*2+c; each lane
// holds one quaternion entry (4 floats) of its half's 2x2 matrix.
// Recurrence: M_new = M_dl * M_w (2x2 quaternion matmul, compile-time signs).
// Carrier unnormalized (dl scaled by stale rn_{t-2}); exact normalization is
// applied to the projected output only (R8 scheme).
// ---------------------------------------------------------------------------
__global__ void __launch_bounds__(256) rotor_rnn_kernel(
    const float* __restrict__ x,      // [B,S,N,D]
    const float* __restrict__ W_in,   // [D, H*32]
    const float* __restrict__ b_in,   // [H*32]
    const float* __restrict__ W_out)  // [H*32, D]
{
    __shared__ float4 sD[2][8][32];   // dl matrices
    __shared__ float4 sW[2][8][32];   // carrier matrices

    const int gw   = (blockIdx.x * blockDim.x + threadIdx.x) >> 5;  // 0..1023
    const int wid  = (threadIdx.x >> 5) & 7;
    const int lane = threadIdx.x & 31;
    const int c  = gw >> 2;            // chain 0..255
    const int hq = gw & 3;             // head quad
    const int h    = hq * 4 + (lane >> 3);
    const int half = (lane >> 2) & 1;  // ideal half
    const int r    = (lane >> 1) & 1;  // matrix row
    const int cl   = lane & 1;         // matrix col
    const int b  = c >> 4;
    const int n  = c & (Nn - 1);
    const int gg = lane & 7;

    // ======== one-time init: weights in matrix coordinates ========
    float wi[4][Dd], bi[4], wo[4][Dd];
#pragma unroll
    for (int k = 0; k < 4; ++k) {
        bi[k] = 0.f;
#pragma unroll
        for (int d = 0; d < Dd; ++d) { wi[k][d] = 0.f; wo[k][d] = 0.f; }
    }

#pragma unroll
    for (int L = 0; L < 16; ++L) {
        // --- build rho(b_L): all of pat/dA/dB/sA/sB/sgn are compile-time ---
        int pat = 0, dA = 0, dB = 0, sA = 1, sB = 1, sgn = 0;
        unsigned cur = 0;
#pragma unroll
        for (int i = 0; i < 4; ++i) {
            if ((L >> i) & 1) {
                const unsigned fm = (1u << i) | 0x10u;   // f_{i+1} = e_{i+1} e_5
                sgn ^= csn(cur, fm);
                cur ^= fm;
                const int gd  = i;                       // quat dim of generator
                const int gAs = 1, gBs = (i == 0) ? -1 : 1;
                if (pat == 0) {      // diag * anti -> anti
                    sA *= gAs * (QNEG(dA, gd) ? -1 : 1); dA ^= gd;
                    sB *= gBs * (QNEG(dB, gd) ? -1 : 1); dB ^= gd;
                    pat = 1;
                } else {             // anti * anti -> diag
                    sA *= gBs * (QNEG(dA, gd) ? -1 : 1); dA ^= gd;
                    sB *= gAs * (QNEG(dB, gd) ? -1 : 1); dB ^= gd;
                    pat = 0;
                }
            }
        }
        // slot ownership: (pat==0) -> diag entries (0,0)&(1,1); else (0,1)&(1,0)
        const float mine = (((pat == 0) == (r == cl)) ? 1.f : 0.f);
        const float sAf = (float)(sA * (sgn ? -1 : 1));
        const float sBf = (float)(sB * (sgn ? -1 : 1));
        const float fA = (r == 0) ? mine * sAf : 0.f;   // row 0 owns A
        const float fB = (r == 1) ? mine * sBf : 0.f;   // row 1 owns B

        // --- omega-split (half) transform, verbatim from R8 ---
        const unsigned E  = lift4((unsigned)L);
        const unsigned Ed = E ^ 31u;
        const float sIn  = csn(31u, Ed) ? -1.f : 1.f;
        const float sOut = csn(31u, E)  ? -1.f : 1.f;
        const float cIn  = half ? -sIn  : sIn;
        const float cOut = half ? -sOut : sOut;
        const int colE = h * 32 + (int)E;
        const int colD = h * 32 + (int)Ed;

#pragma unroll
        for (int d = 0; d < Dd; ++d) {
            const float vin  = __ldg(W_in + d * 512 + colE) +
                               cIn  * __ldg(W_in + d * 512 + colD);
            const float vout = 0.5f * (__ldg(W_out + colE * Dd + d) +
                               cOut * __ldg(W_out + colD * Dd + d));
            wi[dA][d] = fmaf(fA, vin,  wi[dA][d]);
            wi[dB][d] = fmaf(fB, vin,  wi[dB][d]);
            wo[dA][d] = fmaf(fA, vout, wo[dA][d]);
            wo[dB][d] = fmaf(fB, vout, wo[dB][d]);
        }
        const float vb = __ldg(b_in + colE) + cIn * __ldg(b_in + colD);
        bi[dA] = fmaf(fA, vb, bi[dA]);
        bi[dB] = fmaf(fB, vb, bi[dB]);
    }
    // per-step "+1 on scalar blade" folded into bias: rho(1) = I
    if (r == cl) bi[0] += 1.0f;

    // dl operand pairing (lane indices, constant for the whole loop):
    // dlA pairs local w; dlB pairs neighbor w (lane^2).
    const int diagb = ((lane >> 1) ^ lane) & 1;   // 0 iff r==c
    const int laneA = lane ^ diagb;
    const int laneB = laneA ^ 1;

    // carrier init: 0.5 * Identity per half (psi0 = scalar 1)
    float m0 = (r == cl) ? 0.5f : 0.f, m1 = 0.f, m2 = 0.f, m3 = 0.f;
    float rnA = 1.0f, rnB = 1.0f;

    const float2* xp = (const float2*)(x + ((size_t)(b * Ss) * Nn + n) * Dd);
    float* pw = g_part + ((size_t)c * Ss) * 96 + gg * 16 + h;

    float2 cx01 = __ldg(xp + 0), cx23 = __ldg(xp + 1), cx45 = __ldg(xp + 2);

    for (int t = 0; t < Ss; ++t) {
        const int buf = t & 1;

        // prefetch next x (3x LDG.64, warp-uniform)
        const float2* xn = xp + (Nn * Dd) / 2;
        float2 n01, n23, n45;
        if (t + 1 < Ss) {
            n01 = __ldg(xn + 0); n23 = __ldg(xn + 1); n45 = __ldg(xn + 2);
        } else {
            n01 = make_float2(0.f, 0.f); n23 = n01; n45 = n01;
        }

        // dl (this lane's quat entry of M_dl), scaled by stale rn_{t-2}
        float d0 = bi[0], d1 = bi[1], d2 = bi[2], d3 = bi[3];
        {
            const float xs[6] = {cx01.x, cx01.y, cx23.x, cx23.y, cx45.x, cx45.y};
#pragma unroll
            for (int dd = 0; dd < Dd; ++dd) {
                d0 = fmaf(wi[0][dd], xs[dd], d0);
                d1 = fmaf(wi[1][dd], xs[dd], d1);
                d2 = fmaf(wi[2][dd], xs[dd], d2);
                d3 = fmaf(wi[3][dd], xs[dd], d3);
            }
            d0 *= rnA; d1 *= rnA; d2 *= rnA; d3 *= rnA;
        }

        // publish dl + carrier (double-buffered, one syncwarp per step)
        sD[buf][wid][lane] = make_float4(d0, d1, d2, d3);
        sW[buf][wid][lane] = make_float4(m0, m1, m2, m3);
        __syncwarp();

        const float4 a  = sD[buf][wid][laneA];      // dl paired with local w
        const float4 bq = sD[buf][wid][laneB];      // dl paired with neighbor w
        const float4 wn = sW[buf][wid][lane ^ 2];   // w[r^1][c]

        // M_new[r][c] = a (x) w_local + bq (x) wn   (quaternion products)
        float qa0, qa1, qa2, qa3, qb0, qb1, qb2, qb3;
        qa0 =        a.x * m0;
        qa0 = fmaf(-a.y, m1, qa0); qa0 = fmaf(-a.z, m2, qa0); qa0 = fmaf(-a.w, m3, qa0);
        qa1 =        a.x * m1;
        qa1 = fmaf( a.y, m0, qa1); qa1 = fmaf( a.z, m3, qa1); qa1 = fmaf(-a.w, m2, qa1);
        qa2 =        a.x * m2;
        qa2 = fmaf(-a.y, m3, qa2); qa2 = fmaf( a.z, m0, qa2); qa2 = fmaf( a.w, m1, qa2);
        qa3 =        a.x * m3;
        qa3 = fmaf( a.y, m2, qa3); qa3 = fmaf(-a.z, m1, qa3); qa3 = fmaf( a.w, m0, qa3);

        qb0 =        bq.x * wn.x;
        qb0 = fmaf(-bq.y, wn.y, qb0); qb0 = fmaf(-bq.z, wn.z, qb0); qb0 = fmaf(-bq.w, wn.w, qb0);
        qb1 =        bq.x * wn.y;
        qb1 = fmaf( bq.y, wn.x, qb1); qb1 = fmaf( bq.z, wn.w, qb1); qb1 = fmaf(-bq.w, wn.z, qb1);
        qb2 =        bq.x * wn.z;
        qb2 = fmaf(-bq.y, wn.w, qb2); qb2 = fmaf( bq.z, wn.x, qb2); qb2 = fmaf( bq.w, wn.y, qb2);
        qb3 =        bq.x * wn.w;
        qb3 = fmaf( bq.y, wn.z, qb3); qb3 = fmaf(-bq.z, wn.y, qb3); qb3 = fmaf( bq.w, wn.x, qb3);

        const float nw0 = qa0 + qb0, nw1 = qa1 + qb1;
        const float nw2 = qa2 + qb2, nw3 = qa3 + qb3;

        // ---- off the carrier chain: exact normalize for the output ----
        // |psi|^2 = |Ma|^2 + |Mb|^2 = sum over the head's 8 lanes (no x2!)
        float s = nw0 * nw0 + nw1 * nw1;
        s = fmaf(nw2, nw2, s);
        s = fmaf(nw3, nw3, s);
        s += __shfl_xor_sync(FULLMASK, s, 1);
        s += __shfl_xor_sync(FULLMASK, s, 2);
        s += __shfl_xor_sync(FULLMASK, s, 4);
        s += 1e-12f;
        float rn = rsqrtf(s);
        rn = rn * (1.5f - 0.5f * s * rn * rn);   // one NR step
        const float st0 = nw0 * rn, st1 = nw1 * rn;
        const float st2 = nw2 * rn, st3 = nw3 * rn;

        // projection partials (wo already includes T^{-1} factor 0.5)
        float p0, p1, p2, p3, p4, p5;
        p0 = st0 * wo[0][0]; p1 = st0 * wo[0][1]; p2 = st0 * wo[0][2];
        p3 = st0 * wo[0][3]; p4 = st0 * wo[0][4]; p5 = st0 * wo[0][5];
        p0 = fmaf(st1, wo[1][0], p0); p1 = fmaf(st1, wo[1][1], p1);
        p2 = fmaf(st1, wo[1][2], p2); p3 = fmaf(st1, wo[1][3], p3);
        p4 = fmaf(st1, wo[1][4], p4); p5 = fmaf(st1, wo[1][5], p5);
        p0 = fmaf(st2, wo[2][0], p0); p1 = fmaf(st2, wo[2][1], p1);
        p2 = fmaf(st2, wo[2][2], p2); p3 = fmaf(st2, wo[2][3], p3);
        p4 = fmaf(st2, wo[2][4], p4); p5 = fmaf(st2, wo[2][5], p5);
        p0 = fmaf(st3, wo[3][0], p0); p1 = fmaf(st3, wo[3][1], p1);
        p2 = fmaf(st3, wo[3][2], p2); p3 = fmaf(st3, wo[3][3], p3);
        p4 = fmaf(st3, wo[3][4], p4); p5 = fmaf(st3, wo[3][5], p5);
        // 8-lane (head-wide) butterfly reduce: sums halves + matrix slots
#pragma unroll
        for (int o = 1; o < 8; o <<= 1) {
            p0 += __shfl_xor_sync(FULLMASK, p0, o);
            p1 += __shfl_xor_sync(FULLMASK, p1, o);
            p2 += __shfl_xor_sync(FULLMASK, p2, o);
            p3 += __shfl_xor_sync(FULLMASK, p3, o);
            p4 += __shfl_xor_sync(FULLMASK, p4, o);
            p5 += __shfl_xor_sync(FULLMASK, p5, o);
        }
        const float pv = (gg == 0) ? p0 : (gg == 1) ? p1 : (gg == 2) ? p2
                       : (gg == 3) ? p3 : (gg == 4) ? p4 : p5;
        if (gg < 6) *pw = pv;
        pw += 96;

        // rotate state / scales / inputs
        m0 = nw0; m1 = nw1; m2 = nw2; m3 = nw3;
        rnA = rnB; rnB = rn;
        xp = xn;
        cx01 = n01; cx23 = n23; cx45 = n45;
    }
}

// ---------------------------------------------------------------------------
// Combine: y[row,d] = x[row,d] + b_out[d] + sum_{16 heads} part
// ---------------------------------------------------------------------------
__global__ void __launch_bounds__(256) combine_kernel(
    const float* __restrict__ x,
    const float* __restrict__ b_out,
    float* __restrict__ y)
{
    const int e   = blockIdx.x * blockDim.x + threadIdx.x;  // 0..393215
    const int row = e / 6;              // chain*256 + t
    const int d   = e - row * 6;

    const float4* pp = (const float4*)(g_part + (size_t)row * 96 + d * 16);
    float4 v0 = __ldg(pp + 0);
    float4 v1 = __ldg(pp + 1);
    float4 v2 = __ldg(pp + 2);
    float4 v3 = __ldg(pp + 3);
    float acc = __ldg(b_out + d)
              + ((v0.x + v0.y) + (v0.z + v0.w))
              + ((v1.x + v1.y) + (v1.z + v1.w))
              + ((v2.x + v2.y) + (v2.z + v2.w))
              + ((v3.x + v3.y) + (v3.z + v3.w));

    const int c = row >> 8;
    const int t = row & (Ss - 1);
    const int b = c >> 4;
    const int n = c & (Nn - 1);
    const size_t off = (((size_t)b * Ss + t) * Nn + n) * Dd + d;
    y[off] = __ldg(x + off) + acc;
}

extern "C" void kernel_launch(void* const* d_in, const int* in_sizes, int n_in,
                              void* d_out, int out_size) {
    const float* x     = (const float*)d_in[0];
    const float* W_in  = (const float*)d_in[1];
    const float* b_in  = (const float*)d_in[2];
    const float* W_out = (const float*)d_in[3];
    const float* b_out = (const float*)d_in[4];
    float* y = (float*)d_out;

    // Phase 1: 1024 warps, M2(H) recurrence + fused projection
    rotor_rnn_kernel<<<128, 256>>>(x, W_in, b_in, W_out);
    // Phase 2: combine (65536 rows x 6)
    combine_kernel<<<1536, 256>>>(x, b_out, y);
}

// round 13
// speedup vs baseline: 1.7514x; 1.4323x over previous
#include <cuda_runtime.h>

#define FULLMASK 0xffffffffu

// Problem dims (fixed by the dataset)
#define Bb 16
#define Ss 256
#define Nn 16
#define Dd 6

// Per-row projection partials, layout [row][d*16 + head] = 25 MB
__device__ float g_part[(size_t)256 * 256 * 96];

// ---- Clifford sign machinery (5-bit blade masks, matches reference) ----
__host__ __device__ constexpr unsigned popc5(unsigned v) {
    v &= 31u;
    return (v & 1u) + ((v >> 1) & 1u) + ((v >> 2) & 1u) + ((v >> 3) & 1u) + ((v >> 4) & 1u);
}
__host__ __device__ constexpr int csn(unsigned a, unsigned b) {
    a >>= 1; int s = 0;
    while (a) { s += (int)popc5(a & b); a >>= 1; }
    return s & 1;
}
__host__ __device__ constexpr unsigned lift4(unsigned L) {
    L &= 15u;
    unsigned p = (L ^ (L >> 1) ^ (L >> 2) ^ (L >> 3)) & 1u;
    return L | (p << 4);
}
// quaternion unit product sign: dims XOR; neg iff bit(d1*4+d2) of 0xC6A0
#define QNEG(d1, d2) ((0xC6A0u >> ((d1) * 4 + (d2))) & 1u)

// ---- packed f32x2 helpers ----
__device__ __forceinline__ unsigned long long pk2(float lo, float hi) {
    unsigned long long r;
    asm("mov.b64 %0, {%1, %2};" : "=l"(r) : "f"(lo), "f"(hi));
    return r;
}
#define FMA2(d, a, b, c) \
    asm("fma.rn.f32x2 %0, %1, %2, %3;" : "=l"(d) : "l"(a), "l"(b), "l"(c))
#define MUL2(d, a, b) \
    asm("mul.rn.f32x2 %0, %1, %2;" : "=l"(d) : "l"(a), "l"(b))

// ---------------------------------------------------------------------------
// Rotor recurrence + fused projection, M2(H) representation of each ideal.
// ONE WARP PER BLOCK (load balance: 1024 blocks over 148 SMs).
// lane = h*8 + half*4 + q, q = r*2+c; each lane = one quaternion entry.
// Recurrence: M_new = M_dl * M_w (compile-time signs). Carrier unnormalized
// (dl scaled by stale rn_{t-2}); exact normalization applied post-reduce.
// ---------------------------------------------------------------------------
__global__ void __launch_bounds__(32) rotor_rnn_kernel(
    const float* __restrict__ x,      // [B,S,N,D]
    const float* __restrict__ W_in,   // [D, H*32]
    const float* __restrict__ b_in,   // [H*32]
    const float* __restrict__ W_out)  // [H*32, D]
{
    __shared__ float4 sD[2][32];          // dl matrices
    __shared__ float4 sW[2][32];          // carrier matrices
    __shared__ float  sR[2][32][8];       // projection partials (6 used, pad 8)

    const int gw   = blockIdx.x;          // 0..1023
    const int lane = threadIdx.x & 31;
    const int c  = gw >> 2;                // chain 0..255
    const int hq = gw & 3;                 // head quad
    const int h    = hq * 4 + (lane >> 3);
    const int half = (lane >> 2) & 1;      // ideal half
    const int r    = (lane >> 1) & 1;      // matrix row
    const int cl   = lane & 1;             // matrix col
    const int b  = c >> 4;
    const int n  = c & (Nn - 1);
    const int gg = lane & 7;
    const int hb = lane & 24;              // head's lane base

    // ======== one-time init: weights in matrix coordinates ========
    float wi[4][Dd], bi[4], wo[4][Dd];
#pragma unroll
    for (int k = 0; k < 4; ++k) {
        bi[k] = 0.f;
#pragma unroll
        for (int d = 0; d < Dd; ++d) { wi[k][d] = 0.f; wo[k][d] = 0.f; }
    }

#pragma unroll
    for (int L = 0; L < 16; ++L) {
        // --- build rho(b_L): pat/dA/dB/sA/sB/sgn all compile-time ---
        int pat = 0, dA = 0, dB = 0, sA = 1, sB = 1, sgn = 0;
        unsigned cur = 0;
#pragma unroll
        for (int i = 0; i < 4; ++i) {
            if ((L >> i) & 1) {
                const unsigned fm = (1u << i) | 0x10u;   // f_{i+1} = e_{i+1} e_5
                sgn ^= csn(cur, fm);
                cur ^= fm;
                const int gd  = i;
                const int gAs = 1, gBs = (i == 0) ? -1 : 1;
                if (pat == 0) {
                    sA *= gAs * (QNEG(dA, gd) ? -1 : 1); dA ^= gd;
                    sB *= gBs * (QNEG(dB, gd) ? -1 : 1); dB ^= gd;
                    pat = 1;
                } else {
                    sA *= gBs * (QNEG(dA, gd) ? -1 : 1); dA ^= gd;
                    sB *= gAs * (QNEG(dB, gd) ? -1 : 1); dB ^= gd;
                    pat = 0;
                }
            }
        }
        const float mine = (((pat == 0) == (r == cl)) ? 1.f : 0.f);
        const float sAf = (float)(sA * (sgn ? -1 : 1));
        const float sBf = (float)(sB * (sgn ? -1 : 1));
        const float fA = (r == 0) ? mine * sAf : 0.f;
        const float fB = (r == 1) ? mine * sBf : 0.f;

        // --- omega-split (half) transform ---
        const unsigned E  = lift4((unsigned)L);
        const unsigned Ed = E ^ 31u;
        const float sIn  = csn(31u, Ed) ? -1.f : 1.f;
        const float sOut = csn(31u, E)  ? -1.f : 1.f;
        const float cIn  = half ? -sIn  : sIn;
        const float cOut = half ? -sOut : sOut;
        const int colE = h * 32 + (int)E;
        const int colD = h * 32 + (int)Ed;

#pragma unroll
        for (int d = 0; d < Dd; ++d) {
            const float vin  = __ldg(W_in + d * 512 + colE) +
                               cIn  * __ldg(W_in + d * 512 + colD);
            const float vout = 0.5f * (__ldg(W_out + colE * Dd + d) +
                               cOut * __ldg(W_out + colD * Dd + d));
            wi[dA][d] = fmaf(fA, vin,  wi[dA][d]);
            wi[dB][d] = fmaf(fB, vin,  wi[dB][d]);
            wo[dA][d] = fmaf(fA, vout, wo[dA][d]);
            wo[dB][d] = fmaf(fB, vout, wo[dB][d]);
        }
        const float vb = __ldg(b_in + colE) + cIn * __ldg(b_in + colD);
        bi[dA] = fmaf(fA, vb, bi[dA]);
        bi[dB] = fmaf(fB, vb, bi[dB]);
    }
    // per-step "+1 on scalar blade" folded into bias: rho(1) = I
    if (r == cl) bi[0] += 1.0f;

    // pre-packed output weights: woP[k][j] = (wo[k][2j], wo[k][2j+1])
    unsigned long long woP[4][3];
#pragma unroll
    for (int k = 0; k < 4; ++k)
#pragma unroll
        for (int j = 0; j < 3; ++j)
            woP[k][j] = pk2(wo[k][2 * j], wo[k][2 * j + 1]);

    // dl operand pairing (constant lane indices)
    const int diagb = ((lane >> 1) ^ lane) & 1;   // 0 iff r==c
    const int laneA = lane ^ diagb;
    const int laneB = laneA ^ 1;

    // carrier init: 0.5 * Identity per half (psi0 = scalar 1)
    float m0 = (r == cl) ? 0.5f : 0.f, m1 = 0.f, m2 = 0.f, m3 = 0.f;
    float rnA = 1.0f, rnB = 1.0f;

    const float2* xp = (const float2*)(x + ((size_t)(b * Ss) * Nn + n) * Dd);
    float* pw = g_part + ((size_t)c * Ss) * 96 + gg * 16 + h;

    float2 cx01 = __ldg(xp + 0), cx23 = __ldg(xp + 1), cx45 = __ldg(xp + 2);

    for (int t = 0; t < Ss; ++t) {
        const int buf = t & 1;

        // prefetch next x (3x LDG.64, warp-uniform)
        const float2* xn = xp + (Nn * Dd) / 2;
        float2 n01, n23, n45;
        if (t + 1 < Ss) {
            n01 = __ldg(xn + 0); n23 = __ldg(xn + 1); n45 = __ldg(xn + 2);
        } else {
            n01 = make_float2(0.f, 0.f); n23 = n01; n45 = n01;
        }

        // dl (this lane's quat entry of M_dl), scaled by stale rn_{t-2}
        float d0 = bi[0], d1 = bi[1], d2 = bi[2], d3 = bi[3];
        {
            const float xs[6] = {cx01.x, cx01.y, cx23.x, cx23.y, cx45.x, cx45.y};
#pragma unroll
            for (int dd = 0; dd < Dd; ++dd) {
                d0 = fmaf(wi[0][dd], xs[dd], d0);
                d1 = fmaf(wi[1][dd], xs[dd], d1);
                d2 = fmaf(wi[2][dd], xs[dd], d2);
                d3 = fmaf(wi[3][dd], xs[dd], d3);
            }
            d0 *= rnA; d1 *= rnA; d2 *= rnA; d3 *= rnA;
        }

        // publish dl + carrier (double-buffered)
        sD[buf][lane] = make_float4(d0, d1, d2, d3);
        sW[buf][lane] = make_float4(m0, m1, m2, m3);
        __syncwarp();

        const float4 a  = sD[buf][laneA];      // dl paired with local w
        const float4 bq = sD[buf][laneB];      // dl paired with neighbor w
        const float4 wn = sW[buf][lane ^ 2];   // w[r^1][c]

        // M_new[r][c] = a (x) w_local + bq (x) wn  (quaternion products)
        float qa0, qa1, qa2, qa3, qb0, qb1, qb2, qb3;
        qa0 =        a.x * m0;
        qa0 = fmaf(-a.y, m1, qa0); qa0 = fmaf(-a.z, m2, qa0); qa0 = fmaf(-a.w, m3, qa0);
        qa1 =        a.x * m1;
        qa1 = fmaf( a.y, m0, qa1); qa1 = fmaf( a.z, m3, qa1); qa1 = fmaf(-a.w, m2, qa1);
        qa2 =        a.x * m2;
        qa2 = fmaf(-a.y, m3, qa2); qa2 = fmaf( a.z, m0, qa2); qa2 = fmaf( a.w, m1, qa2);
        qa3 =        a.x * m3;
        qa3 = fmaf( a.y, m2, qa3); qa3 = fmaf(-a.z, m1, qa3); qa3 = fmaf( a.w, m0, qa3);

        qb0 =        bq.x * wn.x;
        qb0 = fmaf(-bq.y, wn.y, qb0); qb0 = fmaf(-bq.z, wn.z, qb0); qb0 = fmaf(-bq.w, wn.w, qb0);
        qb1 =        bq.x * wn.y;
        qb1 = fmaf( bq.y, wn.x, qb1); qb1 = fmaf( bq.z, wn.w, qb1); qb1 = fmaf(-bq.w, wn.z, qb1);
        qb2 =        bq.x * wn.z;
        qb2 = fmaf(-bq.y, wn.w, qb2); qb2 = fmaf( bq.z, wn.x, qb2); qb2 = fmaf( bq.w, wn.y, qb2);
        qb3 =        bq.x * wn.w;
        qb3 = fmaf( bq.y, wn.z, qb3); qb3 = fmaf(-bq.z, wn.y, qb3); qb3 = fmaf( bq.w, wn.x, qb3);

        const float nw0 = qa0 + qb0, nw1 = qa1 + qb1;
        const float nw2 = qa2 + qb2, nw3 = qa3 + qb3;

        // ---- head norm (rn uniform per head; consumed post-reduce) ----
        float s = nw0 * nw0 + nw1 * nw1;
        s = fmaf(nw2, nw2, s);
        s = fmaf(nw3, nw3, s);
        s += __shfl_xor_sync(FULLMASK, s, 1);
        s += __shfl_xor_sync(FULLMASK, s, 2);
        s += __shfl_xor_sync(FULLMASK, s, 4);
        s += 1e-12f;
        float rn = rsqrtf(s);
        rn = rn * (1.5f - 0.5f * s * rn * rn);   // one NR step

        // ---- projection partials on RAW nw, packed f32x2 ----
        const unsigned long long w0p = pk2(nw0, nw0);
        const unsigned long long w1p = pk2(nw1, nw1);
        const unsigned long long w2p = pk2(nw2, nw2);
        const unsigned long long w3p = pk2(nw3, nw3);
        unsigned long long p01, p23, p45;
        MUL2(p01, w0p, woP[0][0]);
        MUL2(p23, w0p, woP[0][1]);
        MUL2(p45, w0p, woP[0][2]);
        FMA2(p01, w1p, woP[1][0], p01);
        FMA2(p23, w1p, woP[1][1], p23);
        FMA2(p45, w1p, woP[1][2], p45);
        FMA2(p01, w2p, woP[2][0], p01);
        FMA2(p23, w2p, woP[2][1], p23);
        FMA2(p45, w2p, woP[2][2], p45);
        FMA2(p01, w3p, woP[3][0], p01);
        FMA2(p23, w3p, woP[3][1], p23);
        FMA2(p45, w3p, woP[3][2], p45);

        // store partials (3x STS.64), transpose-reduce via smem
        unsigned long long* rrow = (unsigned long long*)&sR[buf][lane][0];
        rrow[0] = p01; rrow[1] = p23; rrow[2] = p45;
        __syncwarp();

        float acc = sR[buf][hb | 0][gg];
        acc += sR[buf][hb | 1][gg];
        acc += sR[buf][hb | 2][gg];
        acc += sR[buf][hb | 3][gg];
        acc += sR[buf][hb | 4][gg];
        acc += sR[buf][hb | 5][gg];
        acc += sR[buf][hb | 6][gg];
        acc += sR[buf][hb | 7][gg];
        if (gg < 6) *pw = acc * rn;
        pw += 96;

        // rotate state / scales / inputs
        m0 = nw0; m1 = nw1; m2 = nw2; m3 = nw3;
        rnA = rnB; rnB = rn;
        xp = xn;
        cx01 = n01; cx23 = n23; cx45 = n45;
    }
}

// ---------------------------------------------------------------------------
// Combine: y[row,d] = x[row,d] + b_out[d] + sum_{16 heads} part
// ---------------------------------------------------------------------------
__global__ void __launch_bounds__(256) combine_kernel(
    const float* __restrict__ x,
    const float* __restrict__ b_out,
    float* __restrict__ y)
{
    const int e   = blockIdx.x * blockDim.x + threadIdx.x;  // 0..393215
    const int row = e / 6;              // chain*256 + t
    const int d   = e - row * 6;

    const float4* pp = (const float4*)(g_part + (size_t)row * 96 + d * 16);
    float4 v0 = __ldg(pp + 0);
    float4 v1 = __ldg(pp + 1);
    float4 v2 = __ldg(pp + 2);
    float4 v3 = __ldg(pp + 3);
    float acc = __ldg(b_out + d)
              + ((v0.x + v0.y) + (v0.z + v0.w))
              + ((v1.x + v1.y) + (v1.z + v1.w))
              + ((v2.x + v2.y) + (v2.z + v2.w))
              + ((v3.x + v3.y) + (v3.z + v3.w));

    const int c = row >> 8;
    const int t = row & (Ss - 1);
    const int b = c >> 4;
    const int n = c & (Nn - 1);
    const size_t off = (((size_t)b * Ss + t) * Nn + n) * Dd + d;
    y[off] = __ldg(x + off) + acc;
}

extern "C" void kernel_launch(void* const* d_in, const int* in_sizes, int n_in,
                              void* d_out, int out_size) {
    const float* x     = (const float*)d_in[0];
    const float* W_in  = (const float*)d_in[1];
    const float* b_in  = (const float*)d_in[2];
    const float* W_out = (const float*)d_in[3];
    const float* b_out = (const float*)d_in[4];
    float* y = (float*)d_out;

    // Phase 1: 1024 one-warp blocks (load-balanced across all 148 SMs)
    rotor_rnn_kernel<<<1024, 32>>>(x, W_in, b_in, W_out);
    // Phase 2: combine (65536 rows x 6)
    combine_kernel<<<1536, 256>>>(x, b_out, y);
}

// round 14
// speedup vs baseline: 2.0611x; 1.1769x over previous
#include <cuda_runtime.h>

#define FULLMASK 0xffffffffu

// Problem dims (fixed by the dataset)
#define Bb 16
#define Ss 256
#define Nn 16
#define Dd 6

// Per-row projection partials, layout [row][d*16 + head] = 25 MB
__device__ float g_part[(size_t)256 * 256 * 96];

// ---- Clifford sign machinery (5-bit blade masks, matches reference) ----
__host__ __device__ constexpr unsigned popc5(unsigned v) {
    v &= 31u;
    return (v & 1u) + ((v >> 1) & 1u) + ((v >> 2) & 1u) + ((v >> 3) & 1u) + ((v >> 4) & 1u);
}
__host__ __device__ constexpr int csn(unsigned a, unsigned b) {
    a >>= 1; int s = 0;
    while (a) { s += (int)popc5(a & b); a >>= 1; }
    return s & 1;
}
__host__ __device__ constexpr unsigned lift4(unsigned L) {
    L &= 15u;
    unsigned p = (L ^ (L >> 1) ^ (L >> 2) ^ (L >> 3)) & 1u;
    return L | (p << 4);
}
// quaternion unit product sign: dims XOR; neg iff bit(d1*4+d2) of 0xC6A0
#define QNEG(d1, d2) ((0xC6A0u >> ((d1) * 4 + (d2))) & 1u)

// ---- packed f32x2 helpers ----
__device__ __forceinline__ unsigned long long pk2(float lo, float hi) {
    unsigned long long r;
    asm("mov.b64 %0, {%1, %2};" : "=l"(r) : "f"(lo), "f"(hi));
    return r;
}
__device__ __forceinline__ void upk2(float& lo, float& hi, unsigned long long v) {
    asm("mov.b64 {%0, %1}, %2;" : "=f"(lo), "=f"(hi) : "l"(v));
}
#define FMA2(d, a, b, c) \
    asm("fma.rn.f32x2 %0, %1, %2, %3;" : "=l"(d) : "l"(a), "l"(b), "l"(c))
#define MUL2(d, a, b) \
    asm("mul.rn.f32x2 %0, %1, %2;" : "=l"(d) : "l"(a), "l"(b))

// ---------------------------------------------------------------------------
// Rotor recurrence + fused projection, M2(H) representation of each ideal.
// ONE WARP PER BLOCK (1024 blocks over 148 SMs).
// lane = h*8 + half*4 + q, q = r*2+c; each lane = one quaternion entry.
// Recurrence: M_new = M_dl * M_w (compile-time signs). Carrier unnormalized
// (dl scaled by stale rn_{t-2}); exact normalization applied post-reduce.
// R14: conflict-free (9-float-row) transpose reduce, carrier exchange via
// shfl, NR step dropped (rn is output-scale only; rsqrt error ~1e-7).
// ---------------------------------------------------------------------------
__global__ void __launch_bounds__(32) rotor_rnn_kernel(
    const float* __restrict__ x,      // [B,S,N,D]
    const float* __restrict__ W_in,   // [D, H*32]
    const float* __restrict__ b_in,   // [H*32]
    const float* __restrict__ W_out)  // [H*32, D]
{
    __shared__ float4 sD[2][32];          // dl matrices
    __shared__ float  sR[2][32][9];       // partials, 9-float rows (bank-safe)

    const int gw   = blockIdx.x;          // 0..1023
    const int lane = threadIdx.x & 31;
    const int c  = gw >> 2;                // chain 0..255
    const int hq = gw & 3;                 // head quad
    const int h    = hq * 4 + (lane >> 3);
    const int half = (lane >> 2) & 1;      // ideal half
    const int r    = (lane >> 1) & 1;      // matrix row
    const int cl   = lane & 1;             // matrix col
    const int b  = c >> 4;
    const int n  = c & (Nn - 1);
    const int gg = lane & 7;
    const int hb = lane & 24;              // head's lane base

    // ======== one-time init: weights in matrix coordinates ========
    float wi[4][Dd], bi[4], wo[4][Dd];
#pragma unroll
    for (int k = 0; k < 4; ++k) {
        bi[k] = 0.f;
#pragma unroll
        for (int d = 0; d < Dd; ++d) { wi[k][d] = 0.f; wo[k][d] = 0.f; }
    }

#pragma unroll
    for (int L = 0; L < 16; ++L) {
        // --- build rho(b_L): pat/dA/dB/sA/sB/sgn all compile-time ---
        int pat = 0, dA = 0, dB = 0, sA = 1, sB = 1, sgn = 0;
        unsigned cur = 0;
#pragma unroll
        for (int i = 0; i < 4; ++i) {
            if ((L >> i) & 1) {
                const unsigned fm = (1u << i) | 0x10u;   // f_{i+1} = e_{i+1} e_5
                sgn ^= csn(cur, fm);
                cur ^= fm;
                const int gd  = i;
                const int gAs = 1, gBs = (i == 0) ? -1 : 1;
                if (pat == 0) {
                    sA *= gAs * (QNEG(dA, gd) ? -1 : 1); dA ^= gd;
                    sB *= gBs * (QNEG(dB, gd) ? -1 : 1); dB ^= gd;
                    pat = 1;
                } else {
                    sA *= gBs * (QNEG(dA, gd) ? -1 : 1); dA ^= gd;
                    sB *= gAs * (QNEG(dB, gd) ? -1 : 1); dB ^= gd;
                    pat = 0;
                }
            }
        }
        const float mine = (((pat == 0) == (r == cl)) ? 1.f : 0.f);
        const float sAf = (float)(sA * (sgn ? -1 : 1));
        const float sBf = (float)(sB * (sgn ? -1 : 1));
        const float fA = (r == 0) ? mine * sAf : 0.f;
        const float fB = (r == 1) ? mine * sBf : 0.f;

        // --- omega-split (half) transform ---
        const unsigned E  = lift4((unsigned)L);
        const unsigned Ed = E ^ 31u;
        const float sIn  = csn(31u, Ed) ? -1.f : 1.f;
        const float sOut = csn(31u, E)  ? -1.f : 1.f;
        const float cIn  = half ? -sIn  : sIn;
        const float cOut = half ? -sOut : sOut;
        const int colE = h * 32 + (int)E;
        const int colD = h * 32 + (int)Ed;

#pragma unroll
        for (int d = 0; d < Dd; ++d) {
            const float vin  = __ldg(W_in + d * 512 + colE) +
                               cIn  * __ldg(W_in + d * 512 + colD);
            const float vout = 0.5f * (__ldg(W_out + colE * Dd + d) +
                               cOut * __ldg(W_out + colD * Dd + d));
            wi[dA][d] = fmaf(fA, vin,  wi[dA][d]);
            wi[dB][d] = fmaf(fB, vin,  wi[dB][d]);
            wo[dA][d] = fmaf(fA, vout, wo[dA][d]);
            wo[dB][d] = fmaf(fB, vout, wo[dB][d]);
        }
        const float vb = __ldg(b_in + colE) + cIn * __ldg(b_in + colD);
        bi[dA] = fmaf(fA, vb, bi[dA]);
        bi[dB] = fmaf(fB, vb, bi[dB]);
    }
    // per-step "+1 on scalar blade" folded into bias: rho(1) = I
    if (r == cl) bi[0] += 1.0f;

    // pre-packed output weights: woP[k][j] = (wo[k][2j], wo[k][2j+1])
    unsigned long long woP[4][3];
#pragma unroll
    for (int k = 0; k < 4; ++k)
#pragma unroll
        for (int j = 0; j < 3; ++j)
            woP[k][j] = pk2(wo[k][2 * j], wo[k][2 * j + 1]);

    // dl operand pairing (constant lane indices)
    const int diagb = ((lane >> 1) ^ lane) & 1;   // 0 iff r==c
    const int laneA = lane ^ diagb;
    const int laneB = laneA ^ 1;

    // carrier init: 0.5 * Identity per half (psi0 = scalar 1)
    float m0 = (r == cl) ? 0.5f : 0.f, m1 = 0.f, m2 = 0.f, m3 = 0.f;
    float rnA = 1.0f, rnB = 1.0f;

    const float2* xp = (const float2*)(x + ((size_t)(b * Ss) * Nn + n) * Dd);
    float* pw = g_part + ((size_t)c * Ss) * 96 + gg * 16 + h;

    float2 cx01 = __ldg(xp + 0), cx23 = __ldg(xp + 1), cx45 = __ldg(xp + 2);

    for (int t = 0; t < Ss; ++t) {
        const int buf = t & 1;

        // prefetch next x (3x LDG.64, warp-uniform)
        const float2* xn = xp + (Nn * Dd) / 2;
        float2 n01, n23, n45;
        if (t + 1 < Ss) {
            n01 = __ldg(xn + 0); n23 = __ldg(xn + 1); n45 = __ldg(xn + 2);
        } else {
            n01 = make_float2(0.f, 0.f); n23 = n01; n45 = n01;
        }

        // dl (this lane's quat entry of M_dl), scaled by stale rn_{t-2}
        float d0 = bi[0], d1 = bi[1], d2 = bi[2], d3 = bi[3];
        {
            const float xs[6] = {cx01.x, cx01.y, cx23.x, cx23.y, cx45.x, cx45.y};
#pragma unroll
            for (int dd = 0; dd < Dd; ++dd) {
                d0 = fmaf(wi[0][dd], xs[dd], d0);
                d1 = fmaf(wi[1][dd], xs[dd], d1);
                d2 = fmaf(wi[2][dd], xs[dd], d2);
                d3 = fmaf(wi[3][dd], xs[dd], d3);
            }
            d0 *= rnA; d1 *= rnA; d2 *= rnA; d3 *= rnA;
        }

        // publish dl (double-buffered)
        sD[buf][lane] = make_float4(d0, d1, d2, d3);
        __syncwarp();

        const float4 a  = sD[buf][laneA];      // dl paired with local w
        const float4 bq = sD[buf][laneB];      // dl paired with neighbor w
        // carrier neighbor w[r^1][c] via shuffle (no smem round-trip)
        float4 wn;
        wn.x = __shfl_xor_sync(FULLMASK, m0, 2);
        wn.y = __shfl_xor_sync(FULLMASK, m1, 2);
        wn.z = __shfl_xor_sync(FULLMASK, m2, 2);
        wn.w = __shfl_xor_sync(FULLMASK, m3, 2);

        // M_new[r][c] = a (x) w_local + bq (x) wn  (quaternion products)
        float qa0, qa1, qa2, qa3, qb0, qb1, qb2, qb3;
        qa0 =        a.x * m0;
        qa0 = fmaf(-a.y, m1, qa0); qa0 = fmaf(-a.z, m2, qa0); qa0 = fmaf(-a.w, m3, qa0);
        qa1 =        a.x * m1;
        qa1 = fmaf( a.y, m0, qa1); qa1 = fmaf( a.z, m3, qa1); qa1 = fmaf(-a.w, m2, qa1);
        qa2 =        a.x * m2;
        qa2 = fmaf(-a.y, m3, qa2); qa2 = fmaf( a.z, m0, qa2); qa2 = fmaf( a.w, m1, qa2);
        qa3 =        a.x * m3;
        qa3 = fmaf( a.y, m2, qa3); qa3 = fmaf(-a.z, m1, qa3); qa3 = fmaf( a.w, m0, qa3);

        qb0 =        bq.x * wn.x;
        qb0 = fmaf(-bq.y, wn.y, qb0); qb0 = fmaf(-bq.z, wn.z, qb0); qb0 = fmaf(-bq.w, wn.w, qb0);
        qb1 =        bq.x * wn.y;
        qb1 = fmaf( bq.y, wn.x, qb1); qb1 = fmaf( bq.z, wn.w, qb1); qb1 = fmaf(-bq.w, wn.z, qb1);
        qb2 =        bq.x * wn.z;
        qb2 = fmaf(-bq.y, wn.w, qb2); qb2 = fmaf( bq.z, wn.x, qb2); qb2 = fmaf( bq.w, wn.y, qb2);
        qb3 =        bq.x * wn.w;
        qb3 = fmaf( bq.y, wn.z, qb3); qb3 = fmaf(-bq.z, wn.y, qb3); qb3 = fmaf( bq.w, wn.x, qb3);

        const float nw0 = qa0 + qb0, nw1 = qa1 + qb1;
        const float nw2 = qa2 + qb2, nw3 = qa3 + qb3;

        // ---- head norm (rn uniform per head; consumed post-reduce) ----
        float s = nw0 * nw0 + nw1 * nw1;
        s = fmaf(nw2, nw2, s);
        s = fmaf(nw3, nw3, s);
        s += __shfl_xor_sync(FULLMASK, s, 1);
        s += __shfl_xor_sync(FULLMASK, s, 2);
        s += __shfl_xor_sync(FULLMASK, s, 4);
        const float rn = rsqrtf(s + 1e-12f);   // output-scale only; no NR

        // ---- projection partials on RAW nw, packed f32x2 ----
        const unsigned long long w0p = pk2(nw0, nw0);
        const unsigned long long w1p = pk2(nw1, nw1);
        const unsigned long long w2p = pk2(nw2, nw2);
        const unsigned long long w3p = pk2(nw3, nw3);
        unsigned long long p01, p23, p45;
        MUL2(p01, w0p, woP[0][0]);
        MUL2(p23, w0p, woP[0][1]);
        MUL2(p45, w0p, woP[0][2]);
        FMA2(p01, w1p, woP[1][0], p01);
        FMA2(p23, w1p, woP[1][1], p23);
        FMA2(p45, w1p, woP[1][2], p45);
        FMA2(p01, w2p, woP[2][0], p01);
        FMA2(p23, w2p, woP[2][1], p23);
        FMA2(p45, w2p, woP[2][2], p45);
        FMA2(p01, w3p, woP[3][0], p01);
        FMA2(p23, w3p, woP[3][1], p23);
        FMA2(p45, w3p, woP[3][2], p45);

        // store partials (6x STS.32, stride-9 rows: conflict-free)
        float f0, f1, f2, f3, f4, f5;
        upk2(f0, f1, p01);
        upk2(f2, f3, p23);
        upk2(f4, f5, p45);
        float* rrow = &sR[buf][lane][0];
        rrow[0] = f0; rrow[1] = f1; rrow[2] = f2;
        rrow[3] = f3; rrow[4] = f4; rrow[5] = f5;
        __syncwarp();

        // transpose-reduce: bank = (hb + 9k + gg) % 32 -> conflict-free
        float acc = sR[buf][hb | 0][gg];
        acc += sR[buf][hb | 1][gg];
        acc += sR[buf][hb | 2][gg];
        acc += sR[buf][hb | 3][gg];
        acc += sR[buf][hb | 4][gg];
        acc += sR[buf][hb | 5][gg];
        acc += sR[buf][hb | 6][gg];
        acc += sR[buf][hb | 7][gg];
        if (gg < 6) *pw = acc * rn;
        pw += 96;

        // rotate state / scales / inputs
        m0 = nw0; m1 = nw1; m2 = nw2; m3 = nw3;
        rnA = rnB; rnB = rn;
        xp = xn;
        cx01 = n01; cx23 = n23; cx45 = n45;
    }
}

// ---------------------------------------------------------------------------
// Combine: y[row,d] = x[row,d] + b_out[d] + sum_{16 heads} part
// ---------------------------------------------------------------------------
__global__ void __launch_bounds__(256) combine_kernel(
    const float* __restrict__ x,
    const float* __restrict__ b_out,
    float* __restrict__ y)
{
    const int e   = blockIdx.x * blockDim.x + threadIdx.x;  // 0..393215
    const int row = e / 6;              // chain*256 + t
    const int d   = e - row * 6;

    const float4* pp = (const float4*)(g_part + (size_t)row * 96 + d * 16);
    float4 v0 = __ldg(pp + 0);
    float4 v1 = __ldg(pp + 1);
    float4 v2 = __ldg(pp + 2);
    float4 v3 = __ldg(pp + 3);
    float acc = __ldg(b_out + d)
              + ((v0.x + v0.y) + (v0.z + v0.w))
              + ((v1.x + v1.y) + (v1.z + v1.w))
              + ((v2.x + v2.y) + (v2.z + v2.w))
              + ((v3.x + v3.y) + (v3.z + v3.w));

    const int c = row >> 8;
    const int t = row & (Ss - 1);
    const int b = c >> 4;
    const int n = c & (Nn - 1);
    const size_t off = (((size_t)b * Ss + t) * Nn + n) * Dd + d;
    y[off] = __ldg(x + off) + acc;
}

extern "C" void kernel_launch(void* const* d_in, const int* in_sizes, int n_in,
                              void* d_out, int out_size) {
    const float* x     = (const float*)d_in[0];
    const float* W_in  = (const float*)d_in[1];
    const float* b_in  = (const float*)d_in[2];
    const float* W_out = (const float*)d_in[3];
    const float* b_out = (const float*)d_in[4];
    float* y = (float*)d_out;

    // Phase 1: 1024 one-warp blocks (load-balanced across all 148 SMs)
    rotor_rnn_kernel<<<1024, 32>>>(x, W_in, b_in, W_out);
    // Phase 2: combine (65536 rows x 6)
    combine_kernel<<<1536, 256>>>(x, b_out, y);
}

// round 15
// speedup vs baseline: 2.3164x; 1.1238x over previous
#include <cuda_runtime.h>

#define FULLMASK 0xffffffffu

// Problem dims (fixed by the dataset)
#define Bb 16
#define Ss 256
#define Nn 16
#define Dd 6

// Per-row projection partials, layout [row][d*16 + head] = 25 MB
__device__ float g_part[(size_t)256 * 256 * 96];

// ---- Clifford sign machinery (5-bit blade masks, matches reference) ----
__host__ __device__ constexpr unsigned popc5(unsigned v) {
    v &= 31u;
    return (v & 1u) + ((v >> 1) & 1u) + ((v >> 2) & 1u) + ((v >> 3) & 1u) + ((v >> 4) & 1u);
}
__host__ __device__ constexpr int csn(unsigned a, unsigned b) {
    a >>= 1; int s = 0;
    while (a) { s += (int)popc5(a & b); a >>= 1; }
    return s & 1;
}
__host__ __device__ constexpr unsigned lift4(unsigned L) {
    L &= 15u;
    unsigned p = (L ^ (L >> 1) ^ (L >> 2) ^ (L >> 3)) & 1u;
    return L | (p << 4);
}
// quaternion unit product sign: dims XOR; neg iff bit(d1*4+d2) of 0xC6A0
#define QNEG(d1, d2) ((0xC6A0u >> ((d1) * 4 + (d2))) & 1u)

// ---- packed f32x2 helpers ----
__device__ __forceinline__ unsigned long long pk2(float lo, float hi) {
    unsigned long long r;
    asm("mov.b64 %0, {%1, %2};" : "=l"(r) : "f"(lo), "f"(hi));
    return r;
}
__device__ __forceinline__ void upk2(float& lo, float& hi, unsigned long long v) {
    asm("mov.b64 {%0, %1}, %2;" : "=f"(lo), "=f"(hi) : "l"(v));
}
#define FMA2(d, a, b, c) \
    asm("fma.rn.f32x2 %0, %1, %2, %3;" : "=l"(d) : "l"(a), "l"(b), "l"(c))
#define MUL2(d, a, b) \
    asm("mul.rn.f32x2 %0, %1, %2;" : "=l"(d) : "l"(a), "l"(b))

// ---------------------------------------------------------------------------
// Rotor recurrence + fused projection, M2(H) representation of each ideal.
// ONE WARP PER BLOCK (1024 blocks over 148 SMs).
// lane = h*8 + half*4 + q, q = r*2+c; each lane = one quaternion entry.
// R15: dl exchange via SHFL.IDX (no smem, no first syncwarp); norm folded
// into the transpose-reduce (7th column of sR); dl block in packed f32x2.
// Carrier unnormalized (dl scaled by stale rn_{t-2}); normalization applied
// as output scale only.
// ---------------------------------------------------------------------------
__global__ void __launch_bounds__(32) rotor_rnn_kernel(
    const float* __restrict__ x,      // [B,S,N,D]
    const float* __restrict__ W_in,   // [D, H*32]
    const float* __restrict__ b_in,   // [H*32]
    const float* __restrict__ W_out)  // [H*32, D]
{
    __shared__ float sR[2][32][9];    // partials + s, 9-float rows (bank-safe)

    const int gw   = blockIdx.x;          // 0..1023
    const int lane = threadIdx.x & 31;
    const int c  = gw >> 2;                // chain 0..255
    const int hq = gw & 3;                 // head quad
    const int h    = hq * 4 + (lane >> 3);
    const int half = (lane >> 2) & 1;      // ideal half
    const int r    = (lane >> 1) & 1;      // matrix row
    const int cl   = lane & 1;             // matrix col
    const int b  = c >> 4;
    const int n  = c & (Nn - 1);
    const int gg = lane & 7;
    const int hb = lane & 24;              // head's lane base

    // ======== one-time init: weights in matrix coordinates ========
    float wi[4][Dd], bi[4], wo[4][Dd];
#pragma unroll
    for (int k = 0; k < 4; ++k) {
        bi[k] = 0.f;
#pragma unroll
        for (int d = 0; d < Dd; ++d) { wi[k][d] = 0.f; wo[k][d] = 0.f; }
    }

#pragma unroll
    for (int L = 0; L < 16; ++L) {
        // --- build rho(b_L): pat/dA/dB/sA/sB/sgn all compile-time ---
        int pat = 0, dA = 0, dB = 0, sA = 1, sB = 1, sgn = 0;
        unsigned cur = 0;
#pragma unroll
        for (int i = 0; i < 4; ++i) {
            if ((L >> i) & 1) {
                const unsigned fm = (1u << i) | 0x10u;   // f_{i+1} = e_{i+1} e_5
                sgn ^= csn(cur, fm);
                cur ^= fm;
                const int gd  = i;
                const int gAs = 1, gBs = (i == 0) ? -1 : 1;
                if (pat == 0) {
                    sA *= gAs * (QNEG(dA, gd) ? -1 : 1); dA ^= gd;
                    sB *= gBs * (QNEG(dB, gd) ? -1 : 1); dB ^= gd;
                    pat = 1;
                } else {
                    sA *= gBs * (QNEG(dA, gd) ? -1 : 1); dA ^= gd;
                    sB *= gAs * (QNEG(dB, gd) ? -1 : 1); dB ^= gd;
                    pat = 0;
                }
            }
        }
        const float mine = (((pat == 0) == (r == cl)) ? 1.f : 0.f);
        const float sAf = (float)(sA * (sgn ? -1 : 1));
        const float sBf = (float)(sB * (sgn ? -1 : 1));
        const float fA = (r == 0) ? mine * sAf : 0.f;
        const float fB = (r == 1) ? mine * sBf : 0.f;

        // --- omega-split (half) transform ---
        const unsigned E  = lift4((unsigned)L);
        const unsigned Ed = E ^ 31u;
        const float sIn  = csn(31u, Ed) ? -1.f : 1.f;
        const float sOut = csn(31u, E)  ? -1.f : 1.f;
        const float cIn  = half ? -sIn  : sIn;
        const float cOut = half ? -sOut : sOut;
        const int colE = h * 32 + (int)E;
        const int colD = h * 32 + (int)Ed;

#pragma unroll
        for (int d = 0; d < Dd; ++d) {
            const float vin  = __ldg(W_in + d * 512 + colE) +
                               cIn  * __ldg(W_in + d * 512 + colD);
            const float vout = 0.5f * (__ldg(W_out + colE * Dd + d) +
                               cOut * __ldg(W_out + colD * Dd + d));
            wi[dA][d] = fmaf(fA, vin,  wi[dA][d]);
            wi[dB][d] = fmaf(fB, vin,  wi[dB][d]);
            wo[dA][d] = fmaf(fA, vout, wo[dA][d]);
            wo[dB][d] = fmaf(fB, vout, wo[dB][d]);
        }
        const float vb = __ldg(b_in + colE) + cIn * __ldg(b_in + colD);
        bi[dA] = fmaf(fA, vb, bi[dA]);
        bi[dB] = fmaf(fB, vb, bi[dB]);
    }
    // per-step "+1 on scalar blade" folded into bias: rho(1) = I
    if (r == cl) bi[0] += 1.0f;

    // packed weights: input (pairs 01 / 23) and output
    unsigned long long wiP01[Dd], wiP23[Dd];
#pragma unroll
    for (int d = 0; d < Dd; ++d) {
        wiP01[d] = pk2(wi[0][d], wi[1][d]);
        wiP23[d] = pk2(wi[2][d], wi[3][d]);
    }
    const unsigned long long biP01 = pk2(bi[0], bi[1]);
    const unsigned long long biP23 = pk2(bi[2], bi[3]);
    unsigned long long woP[4][3];
#pragma unroll
    for (int k = 0; k < 4; ++k)
#pragma unroll
        for (int j = 0; j < 3; ++j)
            woP[k][j] = pk2(wo[k][2 * j], wo[k][2 * j + 1]);

    // dl operand pairing (constant lane indices; both in {lane, lane^1})
    const int diagb = ((lane >> 1) ^ lane) & 1;   // 0 iff r==c
    const int laneA = lane ^ diagb;
    const int laneB = laneA ^ 1;
    const int laneS = hb | 6;                     // lane holding head's s-sum

    // carrier init: 0.5 * Identity per half (psi0 = scalar 1)
    float m0 = (r == cl) ? 0.5f : 0.f, m1 = 0.f, m2 = 0.f, m3 = 0.f;
    float rnA = 1.0f, rnB = 1.0f;

    const float2* xp = (const float2*)(x + ((size_t)(b * Ss) * Nn + n) * Dd);
    float* pw = g_part + ((size_t)c * Ss) * 96 + gg * 16 + h;

    float2 cx01 = __ldg(xp + 0), cx23 = __ldg(xp + 1), cx45 = __ldg(xp + 2);

    for (int t = 0; t < Ss; ++t) {
        const int buf = t & 1;

        // prefetch next x (3x LDG.64, warp-uniform)
        const float2* xn = xp + (Nn * Dd) / 2;
        float2 n01, n23, n45;
        if (t + 1 < Ss) {
            n01 = __ldg(xn + 0); n23 = __ldg(xn + 1); n45 = __ldg(xn + 2);
        } else {
            n01 = make_float2(0.f, 0.f); n23 = n01; n45 = n01;
        }

        // dl (packed f32x2), scaled by stale rn_{t-2}
        unsigned long long d01 = biP01, d23 = biP23;
        {
            const float xs[6] = {cx01.x, cx01.y, cx23.x, cx23.y, cx45.x, cx45.y};
#pragma unroll
            for (int dd = 0; dd < Dd; ++dd) {
                const unsigned long long xb = pk2(xs[dd], xs[dd]);
                FMA2(d01, xb, wiP01[dd], d01);
                FMA2(d23, xb, wiP23[dd], d23);
            }
            const unsigned long long rp = pk2(rnA, rnA);
            MUL2(d01, d01, rp);
            MUL2(d23, d23, rp);
        }
        float d0, d1, d2, d3;
        upk2(d0, d1, d01);
        upk2(d2, d3, d23);

        // dl exchange via SHFL.IDX (a pairs local w; bq pairs neighbor w)
        float4 a, bq;
        a.x  = __shfl_sync(FULLMASK, d0, laneA);
        a.y  = __shfl_sync(FULLMASK, d1, laneA);
        a.z  = __shfl_sync(FULLMASK, d2, laneA);
        a.w  = __shfl_sync(FULLMASK, d3, laneA);
        bq.x = __shfl_sync(FULLMASK, d0, laneB);
        bq.y = __shfl_sync(FULLMASK, d1, laneB);
        bq.z = __shfl_sync(FULLMASK, d2, laneB);
        bq.w = __shfl_sync(FULLMASK, d3, laneB);
        // carrier neighbor w[r^1][c] via shuffle
        float4 wn;
        wn.x = __shfl_xor_sync(FULLMASK, m0, 2);
        wn.y = __shfl_xor_sync(FULLMASK, m1, 2);
        wn.z = __shfl_xor_sync(FULLMASK, m2, 2);
        wn.w = __shfl_xor_sync(FULLMASK, m3, 2);

        // M_new[r][c] = a (x) w_local + bq (x) wn  (quaternion products)
        float qa0, qa1, qa2, qa3, qb0, qb1, qb2, qb3;
        qa0 =        a.x * m0;
        qa0 = fmaf(-a.y, m1, qa0); qa0 = fmaf(-a.z, m2, qa0); qa0 = fmaf(-a.w, m3, qa0);
        qa1 =        a.x * m1;
        qa1 = fmaf( a.y, m0, qa1); qa1 = fmaf( a.z, m3, qa1); qa1 = fmaf(-a.w, m2, qa1);
        qa2 =        a.x * m2;
        qa2 = fmaf(-a.y, m3, qa2); qa2 = fmaf( a.z, m0, qa2); qa2 = fmaf( a.w, m1, qa2);
        qa3 =        a.x * m3;
        qa3 = fmaf( a.y, m2, qa3); qa3 = fmaf(-a.z, m1, qa3); qa3 = fmaf( a.w, m0, qa3);

        qb0 =        bq.x * wn.x;
        qb0 = fmaf(-bq.y, wn.y, qb0); qb0 = fmaf(-bq.z, wn.z, qb0); qb0 = fmaf(-bq.w, wn.w, qb0);
        qb1 =        bq.x * wn.y;
        qb1 = fmaf( bq.y, wn.x, qb1); qb1 = fmaf( bq.z, wn.w, qb1); qb1 = fmaf(-bq.w, wn.z, qb1);
        qb2 =        bq.x * wn.z;
        qb2 = fmaf(-bq.y, wn.w, qb2); qb2 = fmaf( bq.z, wn.x, qb2); qb2 = fmaf( bq.w, wn.y, qb2);
        qb3 =        bq.x * wn.w;
        qb3 = fmaf( bq.y, wn.z, qb3); qb3 = fmaf(-bq.z, wn.y, qb3); qb3 = fmaf( bq.w, wn.x, qb3);

        const float nw0 = qa0 + qb0, nw1 = qa1 + qb1;
        const float nw2 = qa2 + qb2, nw3 = qa3 + qb3;

        // local squared-norm contribution (reduced via the smem transpose)
        float sl = nw0 * nw0 + nw1 * nw1;
        sl = fmaf(nw2, nw2, sl);
        sl = fmaf(nw3, nw3, sl);

        // ---- projection partials on RAW nw, packed f32x2 ----
        const unsigned long long w0p = pk2(nw0, nw0);
        const unsigned long long w1p = pk2(nw1, nw1);
        const unsigned long long w2p = pk2(nw2, nw2);
        const unsigned long long w3p = pk2(nw3, nw3);
        unsigned long long p01, p23, p45;
        MUL2(p01, w0p, woP[0][0]);
        MUL2(p23, w0p, woP[0][1]);
        MUL2(p45, w0p, woP[0][2]);
        FMA2(p01, w1p, woP[1][0], p01);
        FMA2(p23, w1p, woP[1][1], p23);
        FMA2(p45, w1p, woP[1][2], p45);
        FMA2(p01, w2p, woP[2][0], p01);
        FMA2(p23, w2p, woP[2][1], p23);
        FMA2(p45, w2p, woP[2][2], p45);
        FMA2(p01, w3p, woP[3][0], p01);
        FMA2(p23, w3p, woP[3][1], p23);
        FMA2(p45, w3p, woP[3][2], p45);

        // store partials + s (7x STS.32, stride-9 rows: conflict-free)
        float f0, f1, f2, f3, f4, f5;
        upk2(f0, f1, p01);
        upk2(f2, f3, p23);
        upk2(f4, f5, p45);
        float* rrow = &sR[buf][lane][0];
        rrow[0] = f0; rrow[1] = f1; rrow[2] = f2;
        rrow[3] = f3; rrow[4] = f4; rrow[5] = f5;
        rrow[6] = sl;
        __syncwarp();

        // transpose-reduce: bank = (hb + 9k + gg) % 32 -> conflict-free
        float acc = sR[buf][hb | 0][gg];
        acc += sR[buf][hb | 1][gg];
        acc += sR[buf][hb | 2][gg];
        acc += sR[buf][hb | 3][gg];
        acc += sR[buf][hb | 4][gg];
        acc += sR[buf][hb | 5][gg];
        acc += sR[buf][hb | 6][gg];
        acc += sR[buf][hb | 7][gg];
        // head norm total rides column 6
        const float sTot = __shfl_sync(FULLMASK, acc, laneS);
        const float rn = rsqrtf(sTot + 1e-12f);   // output-scale only
        if (gg < 6) *pw = acc * rn;
        pw += 96;

        // rotate state / scales / inputs
        m0 = nw0; m1 = nw1; m2 = nw2; m3 = nw3;
        rnA = rnB; rnB = rn;
        xp = xn;
        cx01 = n01; cx23 = n23; cx45 = n45;
    }
}

// ---------------------------------------------------------------------------
// Combine: y[row,d] = x[row,d] + b_out[d] + sum_{16 heads} part
// ---------------------------------------------------------------------------
__global__ void __launch_bounds__(256) combine_kernel(
    const float* __restrict__ x,
    const float* __restrict__ b_out,
    float* __restrict__ y)
{
    const int e   = blockIdx.x * blockDim.x + threadIdx.x;  // 0..393215
    const int row = e / 6;              // chain*256 + t
    const int d   = e - row * 6;

    const float4* pp = (const float4*)(g_part + (size_t)row * 96 + d * 16);
    float4 v0 = __ldg(pp + 0);
    float4 v1 = __ldg(pp + 1);
    float4 v2 = __ldg(pp + 2);
    float4 v3 = __ldg(pp + 3);
    float acc = __ldg(b_out + d)
              + ((v0.x + v0.y) + (v0.z + v0.w))
              + ((v1.x + v1.y) + (v1.z + v1.w))
              + ((v2.x + v2.y) + (v2.z + v2.w))
              + ((v3.x + v3.y) + (v3.z + v3.w));

    const int c = row >> 8;
    const int t = row & (Ss - 1);
    const int b = c >> 4;
    const int n = c & (Nn - 1);
    const size_t off = (((size_t)b * Ss + t) * Nn + n) * Dd + d;
    y[off] = __ldg(x + off) + acc;
}

extern "C" void kernel_launch(void* const* d_in, const int* in_sizes, int n_in,
                              void* d_out, int out_size) {
    const float* x     = (const float*)d_in[0];
    const float* W_in  = (const float*)d_in[1];
    const float* b_in  = (const float*)d_in[2];
    const float* W_out = (const float*)d_in[3];
    const float* b_out = (const float*)d_in[4];
    float* y = (float*)d_out;

    // Phase 1: 1024 one-warp blocks (load-balanced across all 148 SMs)
    rotor_rnn_kernel<<<1024, 32>>>(x, W_in, b_in, W_out);
    // Phase 2: combine (65536 rows x 6)
    combine_kernel<<<1536, 256>>>(x, b_out, y);
}

// round 16
// speedup vs baseline: 2.5731x; 1.1108x over previous
#include <cuda_runtime.h>

#define FULLMASK 0xffffffffu

// Problem dims (fixed by the dataset)
#define Bb 16
#define Ss 256
#define Nn 16
#define Dd 6

// Per-row projection partials, layout [row][hq*6 + d] = 6.3 MB
__device__ float g_part[(size_t)256 * 256 * 24];

// ---- Clifford sign machinery (5-bit blade masks, matches reference) ----
__host__ __device__ constexpr unsigned popc5(unsigned v) {
    v &= 31u;
    return (v & 1u) + ((v >> 1) & 1u) + ((v >> 2) & 1u) + ((v >> 3) & 1u) + ((v >> 4) & 1u);
}
__host__ __device__ constexpr int csn(unsigned a, unsigned b) {
    a >>= 1; int s = 0;
    while (a) { s += (int)popc5(a & b); a >>= 1; }
    return s & 1;
}
__host__ __device__ constexpr unsigned lift4(unsigned L) {
    L &= 15u;
    unsigned p = (L ^ (L >> 1) ^ (L >> 2) ^ (L >> 3)) & 1u;
    return L | (p << 4);
}
// quaternion unit product sign: dims XOR; neg iff bit(d1*4+d2) of 0xC6A0
#define QNEG(d1, d2) ((0xC6A0u >> ((d1) * 4 + (d2))) & 1u)

// ---- packed f32x2 helpers ----
__device__ __forceinline__ unsigned long long pk2(float lo, float hi) {
    unsigned long long r;
    asm("mov.b64 %0, {%1, %2};" : "=l"(r) : "f"(lo), "f"(hi));
    return r;
}
__device__ __forceinline__ void upk2(float& lo, float& hi, unsigned long long v) {
    asm("mov.b64 {%0, %1}, %2;" : "=f"(lo), "=f"(hi) : "l"(v));
}
#define FMA2(d, a, b, c) \
    asm("fma.rn.f32x2 %0, %1, %2, %3;" : "=l"(d) : "l"(a), "l"(b), "l"(c))
#define MUL2(d, a, b) \
    asm("mul.rn.f32x2 %0, %1, %2;" : "=l"(d) : "l"(a), "l"(b))

// ---------------------------------------------------------------------------
// Rotor recurrence + fused projection, M2(H) representation of each ideal.
// ONE WARP PER BLOCK (1024 blocks over 148 SMs).
// lane = h*8 + half*4 + q, q = r*2+c; each lane = one quaternion entry.
// R16: cross-head (quad) reduction in-warp -> 4x smaller partials;
// main loop unrolled x2 (compile-time buf, wider scheduling window).
// Carrier unnormalized (dl scaled by stale rn_{t-2}); normalization applied
// as output scale only.
// ---------------------------------------------------------------------------
__global__ void __launch_bounds__(32) rotor_rnn_kernel(
    const float* __restrict__ x,      // [B,S,N,D]
    const float* __restrict__ W_in,   // [D, H*32]
    const float* __restrict__ b_in,   // [H*32]
    const float* __restrict__ W_out)  // [H*32, D]
{
    __shared__ float sR[2][32][9];    // partials + s, 9-float rows (bank-safe)

    const int gw   = blockIdx.x;          // 0..1023
    const int lane = threadIdx.x & 31;
    const int c  = gw >> 2;                // chain 0..255
    const int hq = gw & 3;                 // head quad
    const int h    = hq * 4 + (lane >> 3);
    const int half = (lane >> 2) & 1;      // ideal half
    const int r    = (lane >> 1) & 1;      // matrix row
    const int cl   = lane & 1;             // matrix col
    const int b  = c >> 4;
    const int n  = c & (Nn - 1);
    const int gg = lane & 7;
    const int hb = lane & 24;              // head's lane base

    // ======== one-time init: weights in matrix coordinates ========
    float wi[4][Dd], bi[4], wo[4][Dd];
#pragma unroll
    for (int k = 0; k < 4; ++k) {
        bi[k] = 0.f;
#pragma unroll
        for (int d = 0; d < Dd; ++d) { wi[k][d] = 0.f; wo[k][d] = 0.f; }
    }

#pragma unroll
    for (int L = 0; L < 16; ++L) {
        // --- build rho(b_L): pat/dA/dB/sA/sB/sgn all compile-time ---
        int pat = 0, dA = 0, dB = 0, sA = 1, sB = 1, sgn = 0;
        unsigned cur = 0;
#pragma unroll
        for (int i = 0; i < 4; ++i) {
            if ((L >> i) & 1) {
                const unsigned fm = (1u << i) | 0x10u;   // f_{i+1} = e_{i+1} e_5
                sgn ^= csn(cur, fm);
                cur ^= fm;
                const int gd  = i;
                const int gAs = 1, gBs = (i == 0) ? -1 : 1;
                if (pat == 0) {
                    sA *= gAs * (QNEG(dA, gd) ? -1 : 1); dA ^= gd;
                    sB *= gBs * (QNEG(dB, gd) ? -1 : 1); dB ^= gd;
                    pat = 1;
                } else {
                    sA *= gBs * (QNEG(dA, gd) ? -1 : 1); dA ^= gd;
                    sB *= gAs * (QNEG(dB, gd) ? -1 : 1); dB ^= gd;
                    pat = 0;
                }
            }
        }
        const float mine = (((pat == 0) == (r == cl)) ? 1.f : 0.f);
        const float sAf = (float)(sA * (sgn ? -1 : 1));
        const float sBf = (float)(sB * (sgn ? -1 : 1));
        const float fA = (r == 0) ? mine * sAf : 0.f;
        const float fB = (r == 1) ? mine * sBf : 0.f;

        // --- omega-split (half) transform ---
        const unsigned E  = lift4((unsigned)L);
        const unsigned Ed = E ^ 31u;
        const float sIn  = csn(31u, Ed) ? -1.f : 1.f;
        const float sOut = csn(31u, E)  ? -1.f : 1.f;
        const float cIn  = half ? -sIn  : sIn;
        const float cOut = half ? -sOut : sOut;
        const int colE = h * 32 + (int)E;
        const int colD = h * 32 + (int)Ed;

#pragma unroll
        for (int d = 0; d < Dd; ++d) {
            const float vin  = __ldg(W_in + d * 512 + colE) +
                               cIn  * __ldg(W_in + d * 512 + colD);
            const float vout = 0.5f * (__ldg(W_out + colE * Dd + d) +
                               cOut * __ldg(W_out + colD * Dd + d));
            wi[dA][d] = fmaf(fA, vin,  wi[dA][d]);
            wi[dB][d] = fmaf(fB, vin,  wi[dB][d]);
            wo[dA][d] = fmaf(fA, vout, wo[dA][d]);
            wo[dB][d] = fmaf(fB, vout, wo[dB][d]);
        }
        const float vb = __ldg(b_in + colE) + cIn * __ldg(b_in + colD);
        bi[dA] = fmaf(fA, vb, bi[dA]);
        bi[dB] = fmaf(fB, vb, bi[dB]);
    }
    // per-step "+1 on scalar blade" folded into bias: rho(1) = I
    if (r == cl) bi[0] += 1.0f;

    // packed weights: input (pairs 01 / 23) and output
    unsigned long long wiP01[Dd], wiP23[Dd];
#pragma unroll
    for (int d = 0; d < Dd; ++d) {
        wiP01[d] = pk2(wi[0][d], wi[1][d]);
        wiP23[d] = pk2(wi[2][d], wi[3][d]);
    }
    const unsigned long long biP01 = pk2(bi[0], bi[1]);
    const unsigned long long biP23 = pk2(bi[2], bi[3]);
    unsigned long long woP[4][3];
#pragma unroll
    for (int k = 0; k < 4; ++k)
#pragma unroll
        for (int j = 0; j < 3; ++j)
            woP[k][j] = pk2(wo[k][2 * j], wo[k][2 * j + 1]);

    // dl operand pairing (constant lane indices; both in {lane, lane^1})
    const int diagb = ((lane >> 1) ^ lane) & 1;   // 0 iff r==c
    const int laneA = lane ^ diagb;
    const int laneB = laneA ^ 1;
    const int laneS = hb | 6;                     // lane holding head's s-sum

    // carrier init: 0.5 * Identity per half (psi0 = scalar 1)
    float m0 = (r == cl) ? 0.5f : 0.f, m1 = 0.f, m2 = 0.f, m3 = 0.f;
    float rnA = 1.0f, rnB = 1.0f;

    const float2* xp = (const float2*)(x + ((size_t)(b * Ss) * Nn + n) * Dd);
    float* pw = g_part + ((size_t)c * Ss) * 24 + hq * 6 + lane;

    float2 cx01 = __ldg(xp + 0), cx23 = __ldg(xp + 1), cx45 = __ldg(xp + 2);

#pragma unroll 2
    for (int t = 0; t < Ss; ++t) {
        const int buf = t & 1;

        // prefetch next x (3x LDG.64, warp-uniform)
        const float2* xn = xp + (Nn * Dd) / 2;
        float2 n01, n23, n45;
        if (t + 1 < Ss) {
            n01 = __ldg(xn + 0); n23 = __ldg(xn + 1); n45 = __ldg(xn + 2);
        } else {
            n01 = make_float2(0.f, 0.f); n23 = n01; n45 = n01;
        }

        // dl (packed f32x2), scaled by stale rn_{t-2}
        unsigned long long d01 = biP01, d23 = biP23;
        {
            const float xs[6] = {cx01.x, cx01.y, cx23.x, cx23.y, cx45.x, cx45.y};
#pragma unroll
            for (int dd = 0; dd < Dd; ++dd) {
                const unsigned long long xb = pk2(xs[dd], xs[dd]);
                FMA2(d01, xb, wiP01[dd], d01);
                FMA2(d23, xb, wiP23[dd], d23);
            }
            const unsigned long long rp = pk2(rnA, rnA);
            MUL2(d01, d01, rp);
            MUL2(d23, d23, rp);
        }
        float d0, d1, d2, d3;
        upk2(d0, d1, d01);
        upk2(d2, d3, d23);

        // dl exchange via SHFL.IDX (a pairs local w; bq pairs neighbor w)
        float4 a, bq;
        a.x  = __shfl_sync(FULLMASK, d0, laneA);
        a.y  = __shfl_sync(FULLMASK, d1, laneA);
        a.z  = __shfl_sync(FULLMASK, d2, laneA);
        a.w  = __shfl_sync(FULLMASK, d3, laneA);
        bq.x = __shfl_sync(FULLMASK, d0, laneB);
        bq.y = __shfl_sync(FULLMASK, d1, laneB);
        bq.z = __shfl_sync(FULLMASK, d2, laneB);
        bq.w = __shfl_sync(FULLMASK, d3, laneB);
        // carrier neighbor w[r^1][c] via shuffle
        float4 wn;
        wn.x = __shfl_xor_sync(FULLMASK, m0, 2);
        wn.y = __shfl_xor_sync(FULLMASK, m1, 2);
        wn.z = __shfl_xor_sync(FULLMASK, m2, 2);
        wn.w = __shfl_xor_sync(FULLMASK, m3, 2);

        // M_new[r][c] = a (x) w_local + bq (x) wn  (quaternion products)
        float qa0, qa1, qa2, qa3, qb0, qb1, qb2, qb3;
        qa0 =        a.x * m0;
        qa0 = fmaf(-a.y, m1, qa0); qa0 = fmaf(-a.z, m2, qa0); qa0 = fmaf(-a.w, m3, qa0);
        qa1 =        a.x * m1;
        qa1 = fmaf( a.y, m0, qa1); qa1 = fmaf( a.z, m3, qa1); qa1 = fmaf(-a.w, m2, qa1);
        qa2 =        a.x * m2;
        qa2 = fmaf(-a.y, m3, qa2); qa2 = fmaf( a.z, m0, qa2); qa2 = fmaf( a.w, m1, qa2);
        qa3 =        a.x * m3;
        qa3 = fmaf( a.y, m2, qa3); qa3 = fmaf(-a.z, m1, qa3); qa3 = fmaf( a.w, m0, qa3);

        qb0 =        bq.x * wn.x;
        qb0 = fmaf(-bq.y, wn.y, qb0); qb0 = fmaf(-bq.z, wn.z, qb0); qb0 = fmaf(-bq.w, wn.w, qb0);
        qb1 =        bq.x * wn.y;
        qb1 = fmaf( bq.y, wn.x, qb1); qb1 = fmaf( bq.z, wn.w, qb1); qb1 = fmaf(-bq.w, wn.z, qb1);
        qb2 =        bq.x * wn.z;
        qb2 = fmaf(-bq.y, wn.w, qb2); qb2 = fmaf( bq.z, wn.x, qb2); qb2 = fmaf( bq.w, wn.y, qb2);
        qb3 =        bq.x * wn.w;
        qb3 = fmaf( bq.y, wn.z, qb3); qb3 = fmaf(-bq.z, wn.y, qb3); qb3 = fmaf( bq.w, wn.x, qb3);

        const float nw0 = qa0 + qb0, nw1 = qa1 + qb1;
        const float nw2 = qa2 + qb2, nw3 = qa3 + qb3;

        // local squared-norm contribution (reduced via the smem transpose)
        float sl = nw0 * nw0 + nw1 * nw1;
        sl = fmaf(nw2, nw2, sl);
        sl = fmaf(nw3, nw3, sl);

        // ---- projection partials on RAW nw, packed f32x2 ----
        const unsigned long long w0p = pk2(nw0, nw0);
        const unsigned long long w1p = pk2(nw1, nw1);
        const unsigned long long w2p = pk2(nw2, nw2);
        const unsigned long long w3p = pk2(nw3, nw3);
        unsigned long long p01, p23, p45;
        MUL2(p01, w0p, woP[0][0]);
        MUL2(p23, w0p, woP[0][1]);
        MUL2(p45, w0p, woP[0][2]);
        FMA2(p01, w1p, woP[1][0], p01);
        FMA2(p23, w1p, woP[1][1], p23);
        FMA2(p45, w1p, woP[1][2], p45);
        FMA2(p01, w2p, woP[2][0], p01);
        FMA2(p23, w2p, woP[2][1], p23);
        FMA2(p45, w2p, woP[2][2], p45);
        FMA2(p01, w3p, woP[3][0], p01);
        FMA2(p23, w3p, woP[3][1], p23);
        FMA2(p45, w3p, woP[3][2], p45);

        // store partials + s (7x STS.32, stride-9 rows: conflict-free)
        float f0, f1, f2, f3, f4, f5;
        upk2(f0, f1, p01);
        upk2(f2, f3, p23);
        upk2(f4, f5, p45);
        float* rrow = &sR[buf][lane][0];
        rrow[0] = f0; rrow[1] = f1; rrow[2] = f2;
        rrow[3] = f3; rrow[4] = f4; rrow[5] = f5;
        rrow[6] = sl;
        __syncwarp();

        // transpose-reduce: bank = (hb + 9k + gg) % 32 -> conflict-free
        float acc = sR[buf][hb | 0][gg];
        acc += sR[buf][hb | 1][gg];
        acc += sR[buf][hb | 2][gg];
        acc += sR[buf][hb | 3][gg];
        acc += sR[buf][hb | 4][gg];
        acc += sR[buf][hb | 5][gg];
        acc += sR[buf][hb | 6][gg];
        acc += sR[buf][hb | 7][gg];
        // head norm total rides column 6
        const float sTot = __shfl_sync(FULLMASK, acc, laneS);
        const float rn = rsqrtf(sTot + 1e-12f);   // output-scale only

        // scale by own head's rn, then sum the quad's 4 heads in-warp
        float p = acc * rn;
        p += __shfl_xor_sync(FULLMASK, p, 8);
        p += __shfl_xor_sync(FULLMASK, p, 16);
        if (lane < 6) *pw = p;
        pw += 24;

        // rotate state / scales / inputs
        m0 = nw0; m1 = nw1; m2 = nw2; m3 = nw3;
        rnA = rnB; rnB = rn;
        xp = xn;
        cx01 = n01; cx23 = n23; cx45 = n45;
    }
}

// ---------------------------------------------------------------------------
// Combine: y[row,d] = x[row,d] + b_out[d] + sum_{4 hq} g_part[row][hq*6+d]
// ---------------------------------------------------------------------------
__global__ void __launch_bounds__(256) combine_kernel(
    const float* __restrict__ x,
    const float* __restrict__ b_out,
    float* __restrict__ y)
{
    const int e   = blockIdx.x * blockDim.x + threadIdx.x;  // 0..393215
    const int row = e / 6;              // chain*256 + t
    const int d   = e - row * 6;

    const float* pp = g_part + (size_t)row * 24 + d;
    float acc = __ldg(b_out + d)
              + (__ldg(pp) + __ldg(pp + 6)) + (__ldg(pp + 12) + __ldg(pp + 18));

    const int c = row >> 8;
    const int t = row & (Ss - 1);
    const int b = c >> 4;
    const int n = c & (Nn - 1);
    const size_t off = (((size_t)b * Ss + t) * Nn + n) * Dd + d;
    y[off] = __ldg(x + off) + acc;
}

extern "C" void kernel_launch(void* const* d_in, const int* in_sizes, int n_in,
                              void* d_out, int out_size) {
    const float* x     = (const float*)d_in[0];
    const float* W_in  = (const float*)d_in[1];
    const float* b_in  = (const float*)d_in[2];
    const float* W_out = (const float*)d_in[3];
    const float* b_out = (const float*)d_in[4];
    float* y = (float*)d_out;

    // Phase 1: 1024 one-warp blocks (load-balanced across all 148 SMs)
    rotor_rnn_kernel<<<1024, 32>>>(x, W_in, b_in, W_out);
    // Phase 2: combine (65536 rows x 6)
    combine_kernel<<<1536, 256>>>(x, b_out, y);
}